// round 9
// baseline (speedup 1.0000x reference)
#include <cuda_runtime.h>
#include <cuda_bf16.h>
#include <cstdint>

// Problem constants
#define BB 2
#define SS 2048
#define DIM 2048
#define NH 16
#define NKV 8
#define HD 128
#define M_ROWS (BB*SS)          // 4096
#define KTILES 64               // K=2048 / 32
#define CD 4096                 // fused QKV output width

// ---------------- scratch (device globals: allocation-free) ----------------
__device__ float g_xp   [(size_t)M_ROWS * DIM];
__device__ float g_attp [(size_t)M_ROWS * DIM];
__device__ float g_wqkvp[(size_t)DIM * CD];           // fused wq|wk|wv (32MB)
__device__ float g_wop  [(size_t)DIM * DIM];
// fragment-major tiles for attention (all bf16 hi/lo now)
__device__ float g_Qr[(size_t)BB * NH  * 32 * 8192];  // A-frags hi/lo
__device__ float g_Kr[(size_t)BB * NKV * 32 * 8192];  // B-frags hi/lo (rope'd)
__device__ float g_Vr[(size_t)BB * NKV * 32 * 8192];  // B-frags hi/lo

// ---------------- PTX helpers (base sm_90 / sm_80 features only!) -----------
__device__ __forceinline__ uint32_t smem_u32(const void* p) {
    uint32_t a;
    asm("{ .reg .u64 t; cvta.to.shared.u64 t, %1; cvt.u32.u64 %0, t; }" : "=r"(a) : "l"(p));
    return a;
}

#define MBAR_INIT(a, cnt) \
    asm volatile("mbarrier.init.shared.b64 [%0], %1;" :: "r"(a), "r"(cnt) : "memory")
#define MBAR_EXPECT_TX(a, b) \
    asm volatile("mbarrier.arrive.expect_tx.shared.b64 _, [%0], %1;" :: "r"(a), "r"(b) : "memory")
#define MBAR_ARRIVE(a) \
    asm volatile("mbarrier.arrive.shared.b64 _, [%0];" :: "r"(a) : "memory")

__device__ __forceinline__ void mbar_wait(uint32_t addr, uint32_t phase) {
    uint32_t done;
    asm volatile(
        "{\n\t.reg .pred p;\n\t"
        "mbarrier.try_wait.parity.acquire.cta.shared::cta.b64 p, [%1], %2;\n\t"
        "selp.b32 %0, 1, 0, p;\n\t}"
        : "=r"(done) : "r"(addr), "r"(phase) : "memory");
    if (!done) {
        asm volatile(
            "{\n\t.reg .pred P1;\n\t"
            "W_%=:\n\t"
            "mbarrier.try_wait.parity.acquire.cta.shared::cta.b64 P1, [%0], %1, 0x989680;\n\t"
            "@P1 bra.uni D_%=;\n\t"
            "bra.uni W_%=;\n\t"
            "D_%=:\n\t}"
            :: "r"(addr), "r"(phase) : "memory");
    }
}
__device__ __forceinline__ void bulk_g2s(uint32_t dst, const void* src, uint32_t bytes, uint32_t mbar) {
    asm volatile(
        "cp.async.bulk.shared::cluster.global.mbarrier::complete_tx::bytes [%0], [%1], %2, [%3];"
        :: "r"(dst), "l"(src), "r"(bytes), "r"(mbar) : "memory");
}
__device__ __forceinline__ void fence_async() {
    asm volatile("fence.proxy.async;" ::: "memory");
}

__device__ __forceinline__ void mma_bf16(float* c, const uint32_t* a, const uint32_t* b) {
    asm volatile(
        "mma.sync.aligned.m16n8k16.row.col.f32.bf16.bf16.f32 "
        "{%0,%1,%2,%3}, {%4,%5,%6,%7}, {%8,%9}, {%0,%1,%2,%3};"
        : "+f"(c[0]), "+f"(c[1]), "+f"(c[2]), "+f"(c[3])
        : "r"(a[0]), "r"(a[1]), "r"(a[2]), "r"(a[3]), "r"(b[0]), "r"(b[1]));
}
#define LDS128(r, addr) \
    asm volatile("ld.shared.v4.b32 {%0,%1,%2,%3}, [%4];" \
        : "=r"((r)[0]), "=r"((r)[1]), "=r"((r)[2]), "=r"((r)[3]) : "r"(addr))

// split fp32 pair into bf16-hi pair and bf16-lo (residual) pair, packed
__device__ __forceinline__ void split2(float x, float y, uint32_t& h, uint32_t& l) {
    __nv_bfloat16 hx = __float2bfloat16_rn(x);
    __nv_bfloat16 hy = __float2bfloat16_rn(y);
    float lx = x - __bfloat162float(hx);
    float ly = y - __bfloat162float(hy);
    __nv_bfloat162 hp = __halves2bfloat162(hx, hy);
    __nv_bfloat162 lp = __floats2bfloat162_rn(lx, ly);
    h = *reinterpret_cast<uint32_t*>(&hp);
    l = *reinterpret_cast<uint32_t*>(&lp);
}

// ---------------- pack A (smem-staged): [M,K] -> bf16 hi/lo A-frag tiles -----
__global__ __launch_bounds__(256) void pack_A_bf16(const float* __restrict__ src,
                                                   float* __restrict__ dst, int K)
{
    __shared__ float sa[128][33];
    const int kc = blockIdx.x, mt = blockIdx.y;
    const int tid = threadIdx.x;
    #pragma unroll
    for (int t = 0; t < 4; t++) {
        int u = tid + 256 * t;
        int r = u >> 3, c4 = u & 7;
        float4 v = *(const float4*)(src + (size_t)(mt * 128 + r) * K + kc * 32 + c4 * 4);
        sa[r][c4 * 4 + 0] = v.x; sa[r][c4 * 4 + 1] = v.y;
        sa[r][c4 * 4 + 2] = v.z; sa[r][c4 * 4 + 3] = v.w;
    }
    __syncthreads();
    uint4* tb = (uint4*)(dst + (size_t)(mt * (K / 32) + kc) * 4096);
    #pragma unroll
    for (int t = 0; t < 2; t++) {
        int u = tid + 256 * t;
        int ks2 = u >> 8, mtg = (u >> 5) & 7, lane = u & 31;
        int ml = mtg * 16 + (lane >> 2);
        int kl = ks2 * 16 + (lane & 3) * 2;
        uint32_t h0,h1,h2,h3,l0,l1,l2,l3;
        split2(sa[ml][kl],         sa[ml][kl + 1],       h0, l0);
        split2(sa[ml + 8][kl],     sa[ml + 8][kl + 1],   h1, l1);
        split2(sa[ml][kl + 8],     sa[ml][kl + 9],       h2, l2);
        split2(sa[ml + 8][kl + 8], sa[ml + 8][kl + 9],   h3, l3);
        int bi = ((ks2 * 8 + mtg) * 2) * 32 + lane;
        tb[bi]      = make_uint4(h0, h1, h2, h3);
        tb[bi + 32] = make_uint4(l0, l1, l2, l3);
    }
}

// ---------------- pack B core (smem-staged) ----------------------------------
__device__ __forceinline__ void pack_B_body(const float* __restrict__ w, int N,
                                            int kc, int ntl, uint4* __restrict__ tb)
{
    __shared__ float sb[32][129];
    const int tid = threadIdx.x;
    #pragma unroll
    for (int t = 0; t < 4; t++) {
        int u = tid + 256 * t;
        int r = u >> 5, c4 = u & 31;
        float4 v = *(const float4*)(w + (size_t)(kc * 32 + r) * N + ntl * 128 + c4 * 4);
        sb[r][c4 * 4 + 0] = v.x; sb[r][c4 * 4 + 1] = v.y;
        sb[r][c4 * 4 + 2] = v.z; sb[r][c4 * 4 + 3] = v.w;
    }
    __syncthreads();
    #pragma unroll
    for (int t = 0; t < 4; t++) {
        int u = tid + 256 * t;
        int ks2 = u >> 9, ntg = (u >> 5) & 15, lane = u & 31;
        int kl = ks2 * 16 + (lane & 3) * 2;
        int nl = ntg * 8 + (lane >> 2);
        uint32_t bh0, bl0, bh1, bl1;
        split2(sb[kl][nl],     sb[kl + 1][nl], bh0, bl0);
        split2(sb[kl + 8][nl], sb[kl + 9][nl], bh1, bl1);
        tb[(ks2 * 16 + ntg) * 32 + lane] = make_uint4(bh0, bh1, bl0, bl1);
    }
}

__global__ __launch_bounds__(256) void pack_B_bf16(const float* __restrict__ w,
                                                   float* __restrict__ dst, int N)
{
    const int kc = blockIdx.x, nt = blockIdx.y;
    pack_B_body(w, N, kc, nt, (uint4*)(dst + (size_t)(nt * KTILES + kc) * 4096));
}

__global__ __launch_bounds__(256) void pack_B_qkv(const float* __restrict__ wq,
                                                  const float* __restrict__ wk,
                                                  const float* __restrict__ wv,
                                                  float* __restrict__ dst)
{
    const int kc = blockIdx.x, nt = blockIdx.y;
    uint4* tb = (uint4*)(dst + (size_t)(nt * KTILES + kc) * 4096);
    if (nt < 16)      pack_B_body(wq, DIM,    kc, nt,      tb);
    else if (nt < 24) pack_B_body(wk, NKV*HD, kc, nt - 16, tb);
    else              pack_B_body(wv, NKV*HD, kc, nt - 24, tb);
}

// ---------------- rope from smem tile ----------------------------------------
#define CPIT 132
__device__ __forceinline__ float rope_s(const float* __restrict__ scs, int row, int hd,
                                        const float* __restrict__ cosp,
                                        const float* __restrict__ sinp, int srow)
{
    int j = hd >> 1;
    float c = cosp[srow * 64 + j];
    float s = sinp[srow * 64 + j];
    float v0 = scs[row * CPIT + (hd & ~1)];
    float v1 = scs[row * CPIT + (hd | 1)];
    return (hd & 1) ? (v0 * s + v1 * c) : (v0 * c - v1 * s);
}

// ---------------- bf16x3 GEMM: C[M,N] = A*B (fp32-accurate) ------------------
#define GSTAGES 3
#define STAGE_BYTES 32768

template <int MODE>
__global__ __launch_bounds__(256, 2) void gemm_mma(
    const float* __restrict__ Ap, const float* __restrict__ Bp,
    float* __restrict__ C, int Ndim, int kTiles,
    float* __restrict__ Qr, float* __restrict__ Kr, float* __restrict__ Vr,
    const float* __restrict__ cosp, const float* __restrict__ sinp)
{
    extern __shared__ float dyn[];
    __shared__ __align__(8) uint64_t mbar[2 * GSTAGES];

    const int tid  = threadIdx.x;
    const int lane = tid & 31;
    const int warp = tid >> 5;
    const int wm = warp >> 2;
    const int wn = warp & 3;
    const int nt = blockIdx.x, mt = blockIdx.y;

    uint32_t sbase = (smem_u32(dyn) + 1023) & ~1023u;
    uint32_t mb = smem_u32(mbar);
    #define FULLB(s)  (mb + (s) * 8)
    #define EMPTYB(s) (mb + (GSTAGES + (s)) * 8)

    if (tid == 0) {
        #pragma unroll
        for (int s = 0; s < GSTAGES; s++) {
            MBAR_INIT(FULLB(s), 1);
            MBAR_INIT(EMPTYB(s), 256);
        }
    }
    __syncthreads();

    const char* At = (const char*)(Ap + (size_t)mt * kTiles * 4096);
    const char* Bt = (const char*)(Bp + (size_t)nt * kTiles * 4096);

    if (tid == 0) {
        fence_async();
        #pragma unroll
        for (int j = 0; j < GSTAGES; j++) {
            MBAR_EXPECT_TX(FULLB(j), STAGE_BYTES);
            bulk_g2s(sbase + j * STAGE_BYTES,         At + (size_t)j * 16384, 16384, FULLB(j));
            bulk_g2s(sbase + j * STAGE_BYTES + 16384, Bt + (size_t)j * 16384, 16384, FULLB(j));
        }
    }

    float acc[4][4][4];
    #pragma unroll
    for (int i = 0; i < 4; i++)
        #pragma unroll
        for (int j = 0; j < 4; j++)
            #pragma unroll
            for (int q = 0; q < 4; q++) acc[i][j][q] = 0.f;

    for (int i = 0; i < kTiles; i++) {
        const int s = i % GSTAGES;
        const uint32_t ph = (i / GSTAGES) & 1;
        mbar_wait(FULLB(s), ph);
        const uint32_t a_base = sbase + s * STAGE_BYTES;
        const uint32_t b_base = a_base + 16384;

        #pragma unroll
        for (int ks = 0; ks < 2; ks++) {
            uint32_t ah[4][4], al[4][4], bf[4][4];
            #pragma unroll
            for (int ii = 0; ii < 4; ii++) {
                LDS128(ah[ii], a_base + (uint32_t)((((ks * 8 + wm * 4 + ii) * 2 + 0) * 32 + lane) * 16));
                LDS128(al[ii], a_base + (uint32_t)((((ks * 8 + wm * 4 + ii) * 2 + 1) * 32 + lane) * 16));
            }
            #pragma unroll
            for (int jj = 0; jj < 4; jj++)
                LDS128(bf[jj], b_base + (uint32_t)(((ks * 16 + wn * 4 + jj) * 32 + lane) * 16));
            #pragma unroll
            for (int ii = 0; ii < 4; ii++)
                #pragma unroll
                for (int jj = 0; jj < 4; jj++) {
                    mma_bf16(acc[ii][jj], ah[ii], &bf[jj][0]);
                    mma_bf16(acc[ii][jj], ah[ii], &bf[jj][2]);
                    mma_bf16(acc[ii][jj], al[ii], &bf[jj][0]);
                }
        }
        MBAR_ARRIVE(EMPTYB(s));
        if (tid == 0) {
            int jn = i + GSTAGES;
            if (jn < kTiles) {
                mbar_wait(EMPTYB(s), ph);
                MBAR_EXPECT_TX(FULLB(s), STAGE_BYTES);
                bulk_g2s(a_base, At + (size_t)jn * 16384, 16384, FULLB(s));
                bulk_g2s(b_base, Bt + (size_t)jn * 16384, 16384, FULLB(s));
            }
        }
    }

    const int r = lane >> 2, cc = lane & 3;

    if (MODE == 0) {
        #pragma unroll
        for (int ii = 0; ii < 4; ii++) {
            int m0 = mt * 128 + wm * 64 + ii * 16 + r;
            float* row0 = C + (size_t)m0 * Ndim + nt * 128 + wn * 32 + 2 * cc;
            float* row1 = row0 + 8 * (size_t)Ndim;
            #pragma unroll
            for (int jj = 0; jj < 4; jj++) {
                *(float2*)(row0 + jj * 8) = make_float2(acc[ii][jj][0], acc[ii][jj][1]);
                *(float2*)(row1 + jj * 8) = make_float2(acc[ii][jj][2], acc[ii][jj][3]);
            }
        }
        return;
    }

    // ---------- MODE 1: fused QKV epilogue ----------
    __syncthreads();
    float* scs = dyn;
    #pragma unroll
    for (int ii = 0; ii < 4; ii++) {
        int rl = wm * 64 + ii * 16 + r;
        int cl = wn * 32 + 2 * cc;
        #pragma unroll
        for (int jj = 0; jj < 4; jj++) {
            *(float2*)&scs[rl * CPIT + cl + jj * 8]       = make_float2(acc[ii][jj][0], acc[ii][jj][1]);
            *(float2*)&scs[(rl + 8) * CPIT + cl + jj * 8] = make_float2(acc[ii][jj][2], acc[ii][jj][3]);
        }
    }
    __syncthreads();

    const int b = mt >> 4;
    const int row_base = mt * 128;

    if (nt < 16) {
        // Q: rope + scale -> bf16 hi/lo A-frags [mtg(4)][ds(8)][hl(2)][lane]
        const float scale = 0.08838834764831845f;
        const int bh = b * 16 + nt;
        #pragma unroll
        for (int qhalf = 0; qhalf < 2; qhalf++) {
            uint4* out = (uint4*)(Qr + ((size_t)bh * 32 + (mt & 15) * 2 + qhalf) * 8192);
            #pragma unroll
            for (int t = 0; t < 4; t++) {
                int u = tid + 256 * t;        // 0..1023
                int mtg = u >> 8, ds = (u >> 5) & 7, l2 = u & 31;
                int rl = qhalf * 64 + mtg * 16 + (l2 >> 2);
                int k  = ds * 16 + (l2 & 3) * 2;
                int s0 = (row_base + rl) & (SS - 1);
                int s1 = (row_base + rl + 8) & (SS - 1);
                uint32_t h0,h1,h2,h3,l0,l1,l2r,l3;
                split2(rope_s(scs, rl,     k,     cosp, sinp, s0) * scale,
                       rope_s(scs, rl,     k + 1, cosp, sinp, s0) * scale, h0, l0);
                split2(rope_s(scs, rl + 8, k,     cosp, sinp, s1) * scale,
                       rope_s(scs, rl + 8, k + 1, cosp, sinp, s1) * scale, h1, l1);
                split2(rope_s(scs, rl,     k + 8, cosp, sinp, s0) * scale,
                       rope_s(scs, rl,     k + 9, cosp, sinp, s0) * scale, h2, l2r);
                split2(rope_s(scs, rl + 8, k + 8, cosp, sinp, s1) * scale,
                       rope_s(scs, rl + 8, k + 9, cosp, sinp, s1) * scale, h3, l3);
                int bi = ((mtg * 8 + ds) * 2) * 32 + l2;
                out[bi]      = make_uint4(h0, h1, h2, h3);
                out[bi + 32] = make_uint4(l0, l1, l2r, l3);
            }
        }
    } else if (nt < 24) {
        // K: rope -> bf16 hi/lo B-frags interleaved [ds(8)][kvg(8)][lane] uint4
        const int bhk = b * 8 + (nt - 16);
        #pragma unroll
        for (int kvhalf = 0; kvhalf < 2; kvhalf++) {
            uint4* out = (uint4*)(Kr + ((size_t)bhk * 32 + (mt & 15) * 2 + kvhalf) * 8192);
            #pragma unroll
            for (int t = 0; t < 8; t++) {
                int u = tid + 256 * t;        // 0..2047
                int ds = u >> 8, kvg = (u >> 5) & 7, l2 = u & 31;
                int rl = kvhalf * 64 + kvg * 8 + (l2 >> 2);
                int d  = ds * 16 + (l2 & 3) * 2;
                int srow = (row_base + rl) & (SS - 1);
                uint32_t bh0, bl0, bh1, bl1;
                split2(rope_s(scs, rl, d,     cosp, sinp, srow),
                       rope_s(scs, rl, d + 1, cosp, sinp, srow), bh0, bl0);
                split2(rope_s(scs, rl, d + 8, cosp, sinp, srow),
                       rope_s(scs, rl, d + 9, cosp, sinp, srow), bh1, bl1);
                out[(ds * 8 + kvg) * 32 + l2] = make_uint4(bh0, bh1, bl0, bl1);
            }
        }
    } else {
        // V: bf16 hi/lo B-frags interleaved [t(4)][ng(16)][lane] uint4
        const int bhk = b * 8 + (nt - 24);
        #pragma unroll
        for (int vhalf = 0; vhalf < 2; vhalf++) {
            uint4* out = (uint4*)(Vr + ((size_t)bhk * 32 + (mt & 15) * 2 + vhalf) * 8192);
            #pragma unroll
            for (int it = 0; it < 8; it++) {
                int u = tid + 256 * it;
                int l2 = u & 31, ng = (u >> 5) & 15, tq = u >> 9;
                int kv0 = vhalf * 64 + tq * 16 + (l2 & 3) * 2;
                int d   = ng * 8 + (l2 >> 2);
                float v00 = scs[kv0 * CPIT + d];
                float v01 = scs[(kv0 + 1) * CPIT + d];
                float v10 = scs[(kv0 + 8) * CPIT + d];
                float v11 = scs[(kv0 + 9) * CPIT + d];
                uint32_t h0, l0, h1, l1;
                split2(v00, v01, h0, l0);
                split2(v10, v11, h1, l1);
                out[(tq * 16 + ng) * 32 + l2] = make_uint4(h0, h1, l0, l1);
            }
        }
    }
}

// ---------------- tensor-core flash attention (all bf16x3) -------------------
// BQ=128 (8 warps), BKV=64, 3-stage ring (K 32KB + V 32KB per stage).
#define ASTAGES 3
#define ATTN_SMEM (ASTAGES * 65536)

__global__ __launch_bounds__(256) void attn_mma(
    const float* __restrict__ Qr, const float* __restrict__ Kr,
    const float* __restrict__ Vr, float* __restrict__ Ap)
{
    extern __shared__ float sm[];
    __shared__ __align__(8) uint64_t bars[2 * ASTAGES];

    const int tid = threadIdx.x;
    const int lane = tid & 31, wq = tid >> 5;
    const int qt = 15 - blockIdx.x;                  // heavy CTAs first
    const int bh = blockIdx.y;
    const int b = bh >> 4, h = bh & 15;
    const int bhk = b * 8 + (h >> 1);
    const int niter = 2 * qt + 2;

    uint32_t sbase = smem_u32(sm);
    uint32_t mb = smem_u32(bars);
    #define AFULL(s)  (mb + (s) * 8)
    #define AEMPTY(s) (mb + (ASTAGES + (s)) * 8)

    // Q bf16 hi/lo fragments -> registers
    uint32_t qh[8][4], ql[8][4];
    {
        const uint4* qsrc = (const uint4*)(Qr + ((size_t)bh * 32 + qt * 2 + (wq >> 2)) * 8192);
        const int mtg = wq & 3;
        #pragma unroll
        for (int ds = 0; ds < 8; ds++) {
            uint4 vh = __ldg(&qsrc[((mtg * 8 + ds) * 2) * 32 + lane]);
            uint4 vl = __ldg(&qsrc[((mtg * 8 + ds) * 2) * 32 + 32 + lane]);
            qh[ds][0] = vh.x; qh[ds][1] = vh.y; qh[ds][2] = vh.z; qh[ds][3] = vh.w;
            ql[ds][0] = vl.x; ql[ds][1] = vl.y; ql[ds][2] = vl.z; ql[ds][3] = vl.w;
        }
    }

    if (tid == 0) {
        #pragma unroll
        for (int s = 0; s < ASTAGES; s++) {
            MBAR_INIT(AFULL(s), 1);
            MBAR_INIT(AEMPTY(s), 256);
        }
    }
    __syncthreads();
    if (tid == 0) {
        fence_async();
        int np = niter < ASTAGES ? niter : ASTAGES;
        for (int j = 0; j < np; j++) {
            MBAR_EXPECT_TX(AFULL(j), 65536);
            bulk_g2s(sbase + j * 65536,         Kr + ((size_t)bhk * 32 + j) * 8192, 32768, AFULL(j));
            bulk_g2s(sbase + j * 65536 + 32768, Vr + ((size_t)bhk * 32 + j) * 8192, 32768, AFULL(j));
        }
    }

    float o[16][4];
    #pragma unroll
    for (int i = 0; i < 16; i++)
        #pragma unroll
        for (int q = 0; q < 4; q++) o[i][q] = 0.f;
    float mr0 = -1e30f, mr1 = -1e30f, lr0 = 0.f, lr1 = 0.f;
    const int r0 = lane >> 2;
    const int c0 = (lane & 3) * 2;
    const int qrow = qt * 128 + wq * 16 + r0;

    for (int kb = 0; kb < niter; kb++) {
        const int s = kb % ASTAGES;
        const uint32_t ph = (kb / ASTAGES) & 1;
        mbar_wait(AFULL(s), ph);
        const uint32_t kbase = sbase + s * 65536;
        const uint32_t vbase = kbase + 32768;

        // QK^T (bf16x3): S[16][64] per warp
        float sc[8][4];
        #pragma unroll
        for (int ng = 0; ng < 8; ng++)
            #pragma unroll
            for (int q = 0; q < 4; q++) sc[ng][q] = 0.f;
        #pragma unroll
        for (int ds = 0; ds < 8; ds++) {
            #pragma unroll
            for (int ng = 0; ng < 8; ng++) {
                uint32_t kf[4];
                LDS128(kf, kbase + (uint32_t)(((ds * 8 + ng) * 32 + lane) * 16));
                mma_bf16(sc[ng], qh[ds], &kf[0]);
                mma_bf16(sc[ng], qh[ds], &kf[2]);
                mma_bf16(sc[ng], ql[ds], &kf[0]);
            }
        }
        if (kb >= 2 * qt) {
            #pragma unroll
            for (int ng = 0; ng < 8; ng++) {
                int col = kb * 64 + ng * 8 + c0;
                if (col     > qrow)     sc[ng][0] = -1e30f;
                if (col + 1 > qrow)     sc[ng][1] = -1e30f;
                if (col     > qrow + 8) sc[ng][2] = -1e30f;
                if (col + 1 > qrow + 8) sc[ng][3] = -1e30f;
            }
        }
        float mA = -1e30f, mB = -1e30f;
        #pragma unroll
        for (int ng = 0; ng < 8; ng++) {
            mA = fmaxf(mA, fmaxf(sc[ng][0], sc[ng][1]));
            mB = fmaxf(mB, fmaxf(sc[ng][2], sc[ng][3]));
        }
        mA = fmaxf(mA, __shfl_xor_sync(0xffffffffu, mA, 1));
        mA = fmaxf(mA, __shfl_xor_sync(0xffffffffu, mA, 2));
        mB = fmaxf(mB, __shfl_xor_sync(0xffffffffu, mB, 1));
        mB = fmaxf(mB, __shfl_xor_sync(0xffffffffu, mB, 2));
        float mnA = fmaxf(mr0, mA), mnB = fmaxf(mr1, mB);
        float fA = __expf(mr0 - mnA), fB = __expf(mr1 - mnB);
        mr0 = mnA; mr1 = mnB;
        float sA = 0.f, sB = 0.f;
        #pragma unroll
        for (int ng = 0; ng < 8; ng++) {
            sc[ng][0] = __expf(sc[ng][0] - mnA);
            sc[ng][1] = __expf(sc[ng][1] - mnA);
            sc[ng][2] = __expf(sc[ng][2] - mnB);
            sc[ng][3] = __expf(sc[ng][3] - mnB);
            sA += sc[ng][0] + sc[ng][1];
            sB += sc[ng][2] + sc[ng][3];
        }
        sA += __shfl_xor_sync(0xffffffffu, sA, 1);
        sA += __shfl_xor_sync(0xffffffffu, sA, 2);
        sB += __shfl_xor_sync(0xffffffffu, sB, 1);
        sB += __shfl_xor_sync(0xffffffffu, sB, 2);
        lr0 = lr0 * fA + sA;
        lr1 = lr1 * fB + sB;
        #pragma unroll
        for (int ng = 0; ng < 16; ng++) {
            o[ng][0] *= fA; o[ng][1] *= fA;
            o[ng][2] *= fB; o[ng][3] *= fB;
        }
        uint32_t aPh[4][4], aPl[4][4];
        #pragma unroll
        for (int t = 0; t < 4; t++) {
            split2(sc[2*t][0],   sc[2*t][1],   aPh[t][0], aPl[t][0]);
            split2(sc[2*t][2],   sc[2*t][3],   aPh[t][1], aPl[t][1]);
            split2(sc[2*t+1][0], sc[2*t+1][1], aPh[t][2], aPl[t][2]);
            split2(sc[2*t+1][2], sc[2*t+1][3], aPh[t][3], aPl[t][3]);
        }
        // PV (exact-P x3)
        #pragma unroll
        for (int t = 0; t < 4; t++) {
            #pragma unroll
            for (int ng = 0; ng < 16; ng++) {
                uint32_t vf[4];
                LDS128(vf, vbase + (uint32_t)(((t * 16 + ng) * 32 + lane) * 16));
                mma_bf16(o[ng], aPh[t], &vf[0]);
                mma_bf16(o[ng], aPl[t], &vf[0]);
                mma_bf16(o[ng], aPh[t], &vf[2]);
            }
        }
        MBAR_ARRIVE(AEMPTY(s));
        if (tid == 0 && kb + ASTAGES < niter) {
            int j = kb + ASTAGES;
            mbar_wait(AEMPTY(s), ph);
            MBAR_EXPECT_TX(AFULL(s), 65536);
            bulk_g2s(kbase, Kr + ((size_t)bhk * 32 + j) * 8192, 32768, AFULL(s));
            bulk_g2s(vbase, Vr + ((size_t)bhk * 32 + j) * 8192, 32768, AFULL(s));
        }
    }

    // epilogue: write WO-gemm A-fragments (bf16 hi/lo)
    float iA = 1.0f / lr0, iB = 1.0f / lr1;
    const int mt = b * 16 + qt;
    #pragma unroll
    for (int t = 0; t < 8; t++) {
        float o0 = o[2*t][0] * iA,   o1 = o[2*t][1] * iA;
        float o2 = o[2*t][2] * iB,   o3 = o[2*t][3] * iB;
        float o4 = o[2*t+1][0] * iA, o5 = o[2*t+1][1] * iA;
        float o6 = o[2*t+1][2] * iB, o7 = o[2*t+1][3] * iB;
        uint32_t h0,h1,h2,h3,l0,l1,l2,l3;
        split2(o0, o1, h0, l0);
        split2(o2, o3, h1, l1);
        split2(o4, o5, h2, l2);
        split2(o6, o7, h3, l3);
        int kglob = h * 128 + t * 16;
        int kc = kglob >> 5, ks2 = t & 1;
        uint4* tb = (uint4*)(Ap + ((size_t)mt * 64 + kc) * 4096);
        int bi = ((ks2 * 8 + wq) * 2) * 32 + lane;
        tb[bi]      = make_uint4(h0, h1, h2, h3);
        tb[bi + 32] = make_uint4(l0, l1, l2, l3);
    }
}

// ---------------- launcher ---------------------------------------------------
extern "C" void kernel_launch(void* const* d_in, const int* in_sizes, int n_in,
                              void* d_out, int out_size)
{
    const float* x    = (const float*)d_in[0];
    const float* fcos = (const float*)d_in[1];
    const float* fsin = (const float*)d_in[2];
    const float* wq   = (const float*)d_in[3];
    const float* wk   = (const float*)d_in[4];
    const float* wv   = (const float*)d_in[5];
    const float* wo   = (const float*)d_in[6];
    float* out = (float*)d_out;

    float *pxp, *pattp, *pwqkvp, *pwop, *pQr, *pKr, *pVr;
    cudaGetSymbolAddress((void**)&pxp, g_xp);
    cudaGetSymbolAddress((void**)&pattp, g_attp);
    cudaGetSymbolAddress((void**)&pwqkvp, g_wqkvp);
    cudaGetSymbolAddress((void**)&pwop, g_wop);
    cudaGetSymbolAddress((void**)&pQr, g_Qr);
    cudaGetSymbolAddress((void**)&pKr, g_Kr);
    cudaGetSymbolAddress((void**)&pVr, g_Vr);

    const size_t gsmem = GSTAGES * STAGE_BYTES + 1024;
    cudaFuncSetAttribute(gemm_mma<0>, cudaFuncAttributeMaxDynamicSharedMemorySize, (int)gsmem);
    cudaFuncSetAttribute(gemm_mma<1>, cudaFuncAttributeMaxDynamicSharedMemorySize, (int)gsmem);
    cudaFuncSetAttribute(attn_mma, cudaFuncAttributeMaxDynamicSharedMemorySize, ATTN_SMEM);

    // packs
    pack_B_qkv<<<dim3(KTILES, 32), 256>>>(wq, wk, wv, pwqkvp);
    pack_B_bf16<<<dim3(KTILES, DIM/128), 256>>>(wo, pwop, DIM);
    pack_A_bf16<<<dim3(KTILES, M_ROWS/128), 256>>>(x, pxp, DIM);

    // fused QKV projection + rope + fragment repack (epilogue)
    gemm_mma<1><<<dim3(CD/128, M_ROWS/128), 256, gsmem>>>(
        pxp, pwqkvp, nullptr, CD, KTILES, pQr, pKr, pVr, fcos, fsin);

    // tensor-core flash attention (all bf16x3, writes WO A-frags)
    attn_mma<<<dim3(16, BB * NH), 256, ATTN_SMEM>>>(pQr, pKr, pVr, pattp);

    // output projection (bf16x3)
    gemm_mma<0><<<dim3(DIM/128, M_ROWS/128), 256, gsmem>>>(
        pattp, pwop, out, DIM, KTILES, nullptr, nullptr, nullptr, nullptr, nullptr);
}

// round 11
// speedup vs baseline: 1.1497x; 1.1497x over previous
#include <cuda_runtime.h>
#include <cuda_bf16.h>
#include <cuda_fp16.h>
#include <cstdint>

// Problem constants
#define BB 2
#define SS 2048
#define DIM 2048
#define NH 16
#define NKV 8
#define HD 128
#define M_ROWS (BB*SS)          // 4096
#define KTILES 64               // K=2048 / 32
#define CD 4096                 // fused QKV output width

// ---------------- scratch (device globals: allocation-free) ----------------
__device__ float g_xp   [(size_t)M_ROWS * DIM];       // A tiles (bf16 hi/lo)
__device__ float g_attp [(size_t)M_ROWS * DIM];       // A tiles (bf16 hi/lo)
__device__ float g_wqkvp[(size_t)DIM * CD];           // B tiles (bf16 hi/lo interleaved)
__device__ float g_wop  [(size_t)DIM * DIM];
// fragment-major tiles for attention (fp16)
__device__ float g_Qr[(size_t)BB * NH  * 32 * 4096];  // A-frags fp16 single (16KB/tile)
__device__ float g_Kr[(size_t)BB * NKV * 32 * 4096];  // B-frags fp16 single (16KB/tile)
__device__ float g_Vr[(size_t)BB * NKV * 32 * 4096];  // B-frags fp16 single (16KB/tile)

// ---------------- PTX helpers (base sm_90 / sm_80 features only!) -----------
__device__ __forceinline__ uint32_t smem_u32(const void* p) {
    uint32_t a;
    asm("{ .reg .u64 t; cvta.to.shared.u64 t, %1; cvt.u32.u64 %0, t; }" : "=r"(a) : "l"(p));
    return a;
}

#define MBAR_INIT(a, cnt) \
    asm volatile("mbarrier.init.shared.b64 [%0], %1;" :: "r"(a), "r"(cnt) : "memory")
#define MBAR_EXPECT_TX(a, b) \
    asm volatile("mbarrier.arrive.expect_tx.shared.b64 _, [%0], %1;" :: "r"(a), "r"(b) : "memory")
#define MBAR_ARRIVE(a) \
    asm volatile("mbarrier.arrive.shared.b64 _, [%0];" :: "r"(a) : "memory")

__device__ __forceinline__ void mbar_wait(uint32_t addr, uint32_t phase) {
    uint32_t done;
    asm volatile(
        "{\n\t.reg .pred p;\n\t"
        "mbarrier.try_wait.parity.acquire.cta.shared::cta.b64 p, [%1], %2;\n\t"
        "selp.b32 %0, 1, 0, p;\n\t}"
        : "=r"(done) : "r"(addr), "r"(phase) : "memory");
    if (!done) {
        asm volatile(
            "{\n\t.reg .pred P1;\n\t"
            "W_%=:\n\t"
            "mbarrier.try_wait.parity.acquire.cta.shared::cta.b64 P1, [%0], %1, 0x989680;\n\t"
            "@P1 bra.uni D_%=;\n\t"
            "bra.uni W_%=;\n\t"
            "D_%=:\n\t}"
            :: "r"(addr), "r"(phase) : "memory");
    }
}
__device__ __forceinline__ void bulk_g2s(uint32_t dst, const void* src, uint32_t bytes, uint32_t mbar) {
    asm volatile(
        "cp.async.bulk.shared::cluster.global.mbarrier::complete_tx::bytes [%0], [%1], %2, [%3];"
        :: "r"(dst), "l"(src), "r"(bytes), "r"(mbar) : "memory");
}
__device__ __forceinline__ void fence_async() {
    asm volatile("fence.proxy.async;" ::: "memory");
}

__device__ __forceinline__ void mma_bf16(float* c, const uint32_t* a, const uint32_t* b) {
    asm volatile(
        "mma.sync.aligned.m16n8k16.row.col.f32.bf16.bf16.f32 "
        "{%0,%1,%2,%3}, {%4,%5,%6,%7}, {%8,%9}, {%0,%1,%2,%3};"
        : "+f"(c[0]), "+f"(c[1]), "+f"(c[2]), "+f"(c[3])
        : "r"(a[0]), "r"(a[1]), "r"(a[2]), "r"(a[3]), "r"(b[0]), "r"(b[1]));
}
__device__ __forceinline__ void mma_f16(float* c, const uint32_t* a, const uint32_t* b) {
    asm volatile(
        "mma.sync.aligned.m16n8k16.row.col.f32.f16.f16.f32 "
        "{%0,%1,%2,%3}, {%4,%5,%6,%7}, {%8,%9}, {%0,%1,%2,%3};"
        : "+f"(c[0]), "+f"(c[1]), "+f"(c[2]), "+f"(c[3])
        : "r"(a[0]), "r"(a[1]), "r"(a[2]), "r"(a[3]), "r"(b[0]), "r"(b[1]));
}
#define LDS128(r, addr) \
    asm volatile("ld.shared.v4.b32 {%0,%1,%2,%3}, [%4];" \
        : "=r"((r)[0]), "=r"((r)[1]), "=r"((r)[2]), "=r"((r)[3]) : "r"(addr))
#define LDS64(r, addr) \
    asm volatile("ld.shared.v2.b32 {%0,%1}, [%2];" \
        : "=r"((r)[0]), "=r"((r)[1]) : "r"(addr))

// bf16 split: fp32 pair -> bf16-hi pair + bf16-lo (residual) pair
__device__ __forceinline__ void split2(float x, float y, uint32_t& h, uint32_t& l) {
    __nv_bfloat16 hx = __float2bfloat16_rn(x);
    __nv_bfloat16 hy = __float2bfloat16_rn(y);
    float lx = x - __bfloat162float(hx);
    float ly = y - __bfloat162float(hy);
    __nv_bfloat162 hp = __halves2bfloat162(hx, hy);
    __nv_bfloat162 lp = __floats2bfloat162_rn(lx, ly);
    h = *reinterpret_cast<uint32_t*>(&hp);
    l = *reinterpret_cast<uint32_t*>(&lp);
}
// fp16 split / pack
__device__ __forceinline__ void split2h(float x, float y, uint32_t& h, uint32_t& l) {
    __half hx = __float2half_rn(x);
    __half hy = __float2half_rn(y);
    float lx = x - __half2float(hx);
    float ly = y - __half2float(hy);
    __half2 hp = __halves2half2(hx, hy);
    __half2 lp = __floats2half2_rn(lx, ly);
    h = *reinterpret_cast<uint32_t*>(&hp);
    l = *reinterpret_cast<uint32_t*>(&lp);
}
__device__ __forceinline__ uint32_t packh(float x, float y) {
    __half2 hp = __floats2half2_rn(x, y);
    return *reinterpret_cast<uint32_t*>(&hp);
}

// ---------------- pack A (smem-staged): [M,K] -> bf16 hi/lo A-frag tiles -----
__global__ __launch_bounds__(256) void pack_A_bf16(const float* __restrict__ src,
                                                   float* __restrict__ dst, int K)
{
    __shared__ float sa[128][33];
    const int kc = blockIdx.x, mt = blockIdx.y;
    const int tid = threadIdx.x;
    #pragma unroll
    for (int t = 0; t < 4; t++) {
        int u = tid + 256 * t;
        int r = u >> 3, c4 = u & 7;
        float4 v = *(const float4*)(src + (size_t)(mt * 128 + r) * K + kc * 32 + c4 * 4);
        sa[r][c4 * 4 + 0] = v.x; sa[r][c4 * 4 + 1] = v.y;
        sa[r][c4 * 4 + 2] = v.z; sa[r][c4 * 4 + 3] = v.w;
    }
    __syncthreads();
    uint4* tb = (uint4*)(dst + (size_t)(mt * (K / 32) + kc) * 4096);
    #pragma unroll
    for (int t = 0; t < 2; t++) {
        int u = tid + 256 * t;
        int ks2 = u >> 8, mtg = (u >> 5) & 7, lane = u & 31;
        int ml = mtg * 16 + (lane >> 2);
        int kl = ks2 * 16 + (lane & 3) * 2;
        uint32_t h0,h1,h2,h3,l0,l1,l2,l3;
        split2(sa[ml][kl],         sa[ml][kl + 1],       h0, l0);
        split2(sa[ml + 8][kl],     sa[ml + 8][kl + 1],   h1, l1);
        split2(sa[ml][kl + 8],     sa[ml][kl + 9],       h2, l2);
        split2(sa[ml + 8][kl + 8], sa[ml + 8][kl + 9],   h3, l3);
        int bi = ((ks2 * 8 + mtg) * 2) * 32 + lane;
        tb[bi]      = make_uint4(h0, h1, h2, h3);
        tb[bi + 32] = make_uint4(l0, l1, l2, l3);
    }
}

// ---------------- pack B core (smem-staged): bf16 hi/lo interleaved ----------
__device__ __forceinline__ void pack_B_body(const float* __restrict__ w, int N,
                                            int kc, int ntl, uint4* __restrict__ tb)
{
    __shared__ float sb[32][129];
    const int tid = threadIdx.x;
    #pragma unroll
    for (int t = 0; t < 4; t++) {
        int u = tid + 256 * t;
        int r = u >> 5, c4 = u & 31;
        float4 v = *(const float4*)(w + (size_t)(kc * 32 + r) * N + ntl * 128 + c4 * 4);
        sb[r][c4 * 4 + 0] = v.x; sb[r][c4 * 4 + 1] = v.y;
        sb[r][c4 * 4 + 2] = v.z; sb[r][c4 * 4 + 3] = v.w;
    }
    __syncthreads();
    #pragma unroll
    for (int t = 0; t < 4; t++) {
        int u = tid + 256 * t;
        int ks2 = u >> 9, ntg = (u >> 5) & 15, lane = u & 31;
        int kl = ks2 * 16 + (lane & 3) * 2;
        int nl = ntg * 8 + (lane >> 2);
        uint32_t bh0, bl0, bh1, bl1;
        split2(sb[kl][nl],     sb[kl + 1][nl], bh0, bl0);
        split2(sb[kl + 8][nl], sb[kl + 9][nl], bh1, bl1);
        tb[(ks2 * 16 + ntg) * 32 + lane] = make_uint4(bh0, bh1, bl0, bl1);
    }
}

__global__ __launch_bounds__(256) void pack_B_bf16(const float* __restrict__ w,
                                                   float* __restrict__ dst, int N)
{
    const int kc = blockIdx.x, nt = blockIdx.y;
    pack_B_body(w, N, kc, nt, (uint4*)(dst + (size_t)(nt * KTILES + kc) * 4096));
}

__global__ __launch_bounds__(256) void pack_B_qkv(const float* __restrict__ wq,
                                                  const float* __restrict__ wk,
                                                  const float* __restrict__ wv,
                                                  float* __restrict__ dst)
{
    const int kc = blockIdx.x, nt = blockIdx.y;
    uint4* tb = (uint4*)(dst + (size_t)(nt * KTILES + kc) * 4096);
    if (nt < 16)      pack_B_body(wq, DIM,    kc, nt,      tb);
    else if (nt < 24) pack_B_body(wk, NKV*HD, kc, nt - 16, tb);
    else              pack_B_body(wv, NKV*HD, kc, nt - 24, tb);
}

// ---------------- rope from smem tile ----------------------------------------
#define CPIT 132
__device__ __forceinline__ float rope_s(const float* __restrict__ scs, int row, int hd,
                                        const float* __restrict__ cosp,
                                        const float* __restrict__ sinp, int srow)
{
    int j = hd >> 1;
    float c = cosp[srow * 64 + j];
    float s = sinp[srow * 64 + j];
    float v0 = scs[row * CPIT + (hd & ~1)];
    float v1 = scs[row * CPIT + (hd | 1)];
    return (hd & 1) ? (v0 * s + v1 * c) : (v0 * c - v1 * s);
}

// ---------------- bf16x3 GEMM: C[M,N] = A*B (fp32-accurate) ------------------
#define GSTAGES 3
#define STAGE_BYTES 32768

template <int MODE>
__global__ __launch_bounds__(256, 2) void gemm_mma(
    const float* __restrict__ Ap, const float* __restrict__ Bp,
    float* __restrict__ C, int Ndim, int kTiles,
    float* __restrict__ Qr, float* __restrict__ Kr, float* __restrict__ Vr,
    const float* __restrict__ cosp, const float* __restrict__ sinp)
{
    extern __shared__ float dyn[];
    __shared__ __align__(8) uint64_t mbar[2 * GSTAGES];

    const int tid  = threadIdx.x;
    const int lane = tid & 31;
    const int warp = tid >> 5;
    const int wm = warp >> 2;
    const int wn = warp & 3;
    const int nt = blockIdx.x, mt = blockIdx.y;

    uint32_t sbase = (smem_u32(dyn) + 1023) & ~1023u;
    uint32_t mb = smem_u32(mbar);
    #define FULLB(s)  (mb + (s) * 8)
    #define EMPTYB(s) (mb + (GSTAGES + (s)) * 8)

    if (tid == 0) {
        #pragma unroll
        for (int s = 0; s < GSTAGES; s++) {
            MBAR_INIT(FULLB(s), 1);
            MBAR_INIT(EMPTYB(s), 256);
        }
    }
    __syncthreads();

    const char* At = (const char*)(Ap + (size_t)mt * kTiles * 4096);
    const char* Bt = (const char*)(Bp + (size_t)nt * kTiles * 4096);

    if (tid == 0) {
        fence_async();
        #pragma unroll
        for (int j = 0; j < GSTAGES; j++) {
            MBAR_EXPECT_TX(FULLB(j), STAGE_BYTES);
            bulk_g2s(sbase + j * STAGE_BYTES,         At + (size_t)j * 16384, 16384, FULLB(j));
            bulk_g2s(sbase + j * STAGE_BYTES + 16384, Bt + (size_t)j * 16384, 16384, FULLB(j));
        }
    }

    float acc[4][4][4];
    #pragma unroll
    for (int i = 0; i < 4; i++)
        #pragma unroll
        for (int j = 0; j < 4; j++)
            #pragma unroll
            for (int q = 0; q < 4; q++) acc[i][j][q] = 0.f;

    for (int i = 0; i < kTiles; i++) {
        const int s = i % GSTAGES;
        const uint32_t ph = (i / GSTAGES) & 1;
        mbar_wait(FULLB(s), ph);
        const uint32_t a_base = sbase + s * STAGE_BYTES;
        const uint32_t b_base = a_base + 16384;

        #pragma unroll
        for (int ks = 0; ks < 2; ks++) {
            uint32_t ah[4][4], al[4][4], bf[4][4];
            #pragma unroll
            for (int ii = 0; ii < 4; ii++) {
                LDS128(ah[ii], a_base + (uint32_t)((((ks * 8 + wm * 4 + ii) * 2 + 0) * 32 + lane) * 16));
                LDS128(al[ii], a_base + (uint32_t)((((ks * 8 + wm * 4 + ii) * 2 + 1) * 32 + lane) * 16));
            }
            #pragma unroll
            for (int jj = 0; jj < 4; jj++)
                LDS128(bf[jj], b_base + (uint32_t)(((ks * 16 + wn * 4 + jj) * 32 + lane) * 16));
            #pragma unroll
            for (int ii = 0; ii < 4; ii++)
                #pragma unroll
                for (int jj = 0; jj < 4; jj++) {
                    mma_bf16(acc[ii][jj], ah[ii], &bf[jj][0]);
                    mma_bf16(acc[ii][jj], ah[ii], &bf[jj][2]);
                    mma_bf16(acc[ii][jj], al[ii], &bf[jj][0]);
                }
        }
        MBAR_ARRIVE(EMPTYB(s));
        if (tid == 0) {
            int jn = i + GSTAGES;
            if (jn < kTiles) {
                mbar_wait(EMPTYB(s), ph);
                MBAR_EXPECT_TX(FULLB(s), STAGE_BYTES);
                bulk_g2s(a_base, At + (size_t)jn * 16384, 16384, FULLB(s));
                bulk_g2s(b_base, Bt + (size_t)jn * 16384, 16384, FULLB(s));
            }
        }
    }

    const int r = lane >> 2, cc = lane & 3;

    if (MODE == 0) {
        #pragma unroll
        for (int ii = 0; ii < 4; ii++) {
            int m0 = mt * 128 + wm * 64 + ii * 16 + r;
            float* row0 = C + (size_t)m0 * Ndim + nt * 128 + wn * 32 + 2 * cc;
            float* row1 = row0 + 8 * (size_t)Ndim;
            #pragma unroll
            for (int jj = 0; jj < 4; jj++) {
                *(float2*)(row0 + jj * 8) = make_float2(acc[ii][jj][0], acc[ii][jj][1]);
                *(float2*)(row1 + jj * 8) = make_float2(acc[ii][jj][2], acc[ii][jj][3]);
            }
        }
        return;
    }

    // ---------- MODE 1: fused QKV epilogue (Q/K/V -> fp16 frag tiles) --------
    __syncthreads();
    float* scs = dyn;
    #pragma unroll
    for (int ii = 0; ii < 4; ii++) {
        int rl = wm * 64 + ii * 16 + r;
        int cl = wn * 32 + 2 * cc;
        #pragma unroll
        for (int jj = 0; jj < 4; jj++) {
            *(float2*)&scs[rl * CPIT + cl + jj * 8]       = make_float2(acc[ii][jj][0], acc[ii][jj][1]);
            *(float2*)&scs[(rl + 8) * CPIT + cl + jj * 8] = make_float2(acc[ii][jj][2], acc[ii][jj][3]);
        }
    }
    __syncthreads();

    const int b = mt >> 4;
    const int row_base = mt * 128;

    if (nt < 16) {
        // Q: rope + scale -> fp16 single A-frags [mtg(4)][ds(8)][lane] uint4 (16KB)
        const float scale = 0.08838834764831845f;
        const int bh = b * 16 + nt;
        #pragma unroll
        for (int qhalf = 0; qhalf < 2; qhalf++) {
            uint4* out = (uint4*)(Qr + ((size_t)bh * 32 + (mt & 15) * 2 + qhalf) * 4096);
            #pragma unroll
            for (int t = 0; t < 4; t++) {
                int u = tid + 256 * t;        // 0..1023
                int mtg = u >> 8, ds = (u >> 5) & 7, l2 = u & 31;
                int rl = qhalf * 64 + mtg * 16 + (l2 >> 2);
                int k  = ds * 16 + (l2 & 3) * 2;
                int s0 = (row_base + rl) & (SS - 1);
                int s1 = (row_base + rl + 8) & (SS - 1);
                uint32_t h0 = packh(rope_s(scs, rl,     k,     cosp, sinp, s0) * scale,
                                    rope_s(scs, rl,     k + 1, cosp, sinp, s0) * scale);
                uint32_t h1 = packh(rope_s(scs, rl + 8, k,     cosp, sinp, s1) * scale,
                                    rope_s(scs, rl + 8, k + 1, cosp, sinp, s1) * scale);
                uint32_t h2 = packh(rope_s(scs, rl,     k + 8, cosp, sinp, s0) * scale,
                                    rope_s(scs, rl,     k + 9, cosp, sinp, s0) * scale);
                uint32_t h3 = packh(rope_s(scs, rl + 8, k + 8, cosp, sinp, s1) * scale,
                                    rope_s(scs, rl + 8, k + 9, cosp, sinp, s1) * scale);
                out[(mtg * 8 + ds) * 32 + l2] = make_uint4(h0, h1, h2, h3);
            }
        }
    } else if (nt < 24) {
        // K: rope -> fp16 single B-frags [ds(8)][kvg(8)][lane] uint2 (16KB)
        const int bhk = b * 8 + (nt - 16);
        #pragma unroll
        for (int kvhalf = 0; kvhalf < 2; kvhalf++) {
            uint2* out = (uint2*)(Kr + ((size_t)bhk * 32 + (mt & 15) * 2 + kvhalf) * 4096);
            #pragma unroll
            for (int t = 0; t < 8; t++) {
                int u = tid + 256 * t;        // 0..2047
                int ds = u >> 8, kvg = (u >> 5) & 7, l2 = u & 31;
                int rl = kvhalf * 64 + kvg * 8 + (l2 >> 2);
                int d  = ds * 16 + (l2 & 3) * 2;
                int srow = (row_base + rl) & (SS - 1);
                uint32_t kh0 = packh(rope_s(scs, rl, d,     cosp, sinp, srow),
                                     rope_s(scs, rl, d + 1, cosp, sinp, srow));
                uint32_t kh1 = packh(rope_s(scs, rl, d + 8, cosp, sinp, srow),
                                     rope_s(scs, rl, d + 9, cosp, sinp, srow));
                out[(ds * 8 + kvg) * 32 + l2] = make_uint2(kh0, kh1);
            }
        }
    } else {
        // V: fp16 single B-frags [ks(4)][ng(16)][lane] uint2 (16KB)
        const int bhk = b * 8 + (nt - 24);
        #pragma unroll
        for (int vhalf = 0; vhalf < 2; vhalf++) {
            uint2* out = (uint2*)(Vr + ((size_t)bhk * 32 + (mt & 15) * 2 + vhalf) * 4096);
            #pragma unroll
            for (int it = 0; it < 8; it++) {
                int u = tid + 256 * it;       // 0..2047
                int l2 = u & 31, ng = (u >> 5) & 15, ks = u >> 9;
                int kv0 = vhalf * 64 + ks * 16 + (l2 & 3) * 2;
                int d   = ng * 8 + (l2 >> 2);
                uint32_t vh0 = packh(scs[kv0 * CPIT + d],       scs[(kv0 + 1) * CPIT + d]);
                uint32_t vh1 = packh(scs[(kv0 + 8) * CPIT + d], scs[(kv0 + 9) * CPIT + d]);
                out[(ks * 16 + ng) * 32 + l2] = make_uint2(vh0, vh1);
            }
        }
    }
}

// ---------------- tensor-core flash attention (fp16 QK + exactP-fp16V PV) ----
// BQ=128 (8 warps), BKV=64, 3-stage ring (K 16KB + V 16KB per stage) = 96KB.
#define ASTAGES 3
#define ATTN_SMEM (ASTAGES * 32768)

__global__ __launch_bounds__(256) void attn_mma(
    const float* __restrict__ Qr, const float* __restrict__ Kr,
    const float* __restrict__ Vr, float* __restrict__ Ap)
{
    extern __shared__ float sm[];
    __shared__ __align__(8) uint64_t bars[2 * ASTAGES];

    const int tid = threadIdx.x;
    const int lane = tid & 31, wq = tid >> 5;
    const int qt = 15 - blockIdx.x;                  // heavy CTAs first
    const int bh = blockIdx.y;
    const int b = bh >> 4, h = bh & 15;
    const int bhk = b * 8 + (h >> 1);
    const int niter = 2 * qt + 2;

    uint32_t sbase = smem_u32(sm);
    uint32_t mb = smem_u32(bars);
    #define AFULL(s)  (mb + (s) * 8)
    #define AEMPTY(s) (mb + (ASTAGES + (s)) * 8)

    // Q fp16 single fragments -> registers (32 regs)
    uint32_t qf[8][4];
    {
        const uint4* qsrc = (const uint4*)(Qr + ((size_t)bh * 32 + qt * 2 + (wq >> 2)) * 4096);
        const int mtg = wq & 3;
        #pragma unroll
        for (int ds = 0; ds < 8; ds++) {
            uint4 v = __ldg(&qsrc[(mtg * 8 + ds) * 32 + lane]);
            qf[ds][0] = v.x; qf[ds][1] = v.y; qf[ds][2] = v.z; qf[ds][3] = v.w;
        }
    }

    if (tid == 0) {
        #pragma unroll
        for (int s = 0; s < ASTAGES; s++) {
            MBAR_INIT(AFULL(s), 1);
            MBAR_INIT(AEMPTY(s), 256);
        }
    }
    __syncthreads();
    if (tid == 0) {
        fence_async();
        int np = niter < ASTAGES ? niter : ASTAGES;
        for (int j = 0; j < np; j++) {
            MBAR_EXPECT_TX(AFULL(j), 32768);
            bulk_g2s(sbase + j * 32768,         Kr + ((size_t)bhk * 32 + j) * 4096, 16384, AFULL(j));
            bulk_g2s(sbase + j * 32768 + 16384, Vr + ((size_t)bhk * 32 + j) * 4096, 16384, AFULL(j));
        }
    }

    float o[16][4];
    #pragma unroll
    for (int i = 0; i < 16; i++)
        #pragma unroll
        for (int q = 0; q < 4; q++) o[i][q] = 0.f;
    float mr0 = -1e30f, mr1 = -1e30f, lr0 = 0.f, lr1 = 0.f;
    const int r0 = lane >> 2;
    const int c0 = (lane & 3) * 2;
    const int qrow = qt * 128 + wq * 16 + r0;

    for (int kb = 0; kb < niter; kb++) {
        const int s = kb % ASTAGES;
        const uint32_t ph = (kb / ASTAGES) & 1;
        mbar_wait(AFULL(s), ph);
        const uint32_t kbase = sbase + s * 32768;
        const uint32_t vbase = kbase + 16384;

        // QK^T (fp16 single x single): 64 mmas
        float sc[8][4];
        #pragma unroll
        for (int ng = 0; ng < 8; ng++)
            #pragma unroll
            for (int q = 0; q < 4; q++) sc[ng][q] = 0.f;
        #pragma unroll
        for (int ds = 0; ds < 8; ds++) {
            #pragma unroll
            for (int ng = 0; ng < 8; ng++) {
                uint32_t kf[2];
                LDS64(kf, kbase + (uint32_t)(((ds * 8 + ng) * 32 + lane) * 8));
                mma_f16(sc[ng], qf[ds], kf);
            }
        }
        if (kb >= 2 * qt) {
            #pragma unroll
            for (int ng = 0; ng < 8; ng++) {
                int col = kb * 64 + ng * 8 + c0;
                if (col     > qrow)     sc[ng][0] = -1e30f;
                if (col + 1 > qrow)     sc[ng][1] = -1e30f;
                if (col     > qrow + 8) sc[ng][2] = -1e30f;
                if (col + 1 > qrow + 8) sc[ng][3] = -1e30f;
            }
        }
        float mA = -1e30f, mB = -1e30f;
        #pragma unroll
        for (int ng = 0; ng < 8; ng++) {
            mA = fmaxf(mA, fmaxf(sc[ng][0], sc[ng][1]));
            mB = fmaxf(mB, fmaxf(sc[ng][2], sc[ng][3]));
        }
        mA = fmaxf(mA, __shfl_xor_sync(0xffffffffu, mA, 1));
        mA = fmaxf(mA, __shfl_xor_sync(0xffffffffu, mA, 2));
        mB = fmaxf(mB, __shfl_xor_sync(0xffffffffu, mB, 1));
        mB = fmaxf(mB, __shfl_xor_sync(0xffffffffu, mB, 2));
        float mnA = fmaxf(mr0, mA), mnB = fmaxf(mr1, mB);
        float fA = __expf(mr0 - mnA), fB = __expf(mr1 - mnB);
        mr0 = mnA; mr1 = mnB;
        float sA = 0.f, sB = 0.f;
        #pragma unroll
        for (int ng = 0; ng < 8; ng++) {
            sc[ng][0] = __expf(sc[ng][0] - mnA);
            sc[ng][1] = __expf(sc[ng][1] - mnA);
            sc[ng][2] = __expf(sc[ng][2] - mnB);
            sc[ng][3] = __expf(sc[ng][3] - mnB);
            sA += sc[ng][0] + sc[ng][1];
            sB += sc[ng][2] + sc[ng][3];
        }
        sA += __shfl_xor_sync(0xffffffffu, sA, 1);
        sA += __shfl_xor_sync(0xffffffffu, sA, 2);
        sB += __shfl_xor_sync(0xffffffffu, sB, 1);
        sB += __shfl_xor_sync(0xffffffffu, sB, 2);
        lr0 = lr0 * fA + sA;
        lr1 = lr1 * fB + sB;
        #pragma unroll
        for (int ng = 0; ng < 16; ng++) {
            o[ng][0] *= fA; o[ng][1] *= fA;
            o[ng][2] *= fB; o[ng][3] *= fB;
        }
        // pack P into fp16 hi/lo A-frags (registers only)
        uint32_t aPh[4][4], aPl[4][4];
        #pragma unroll
        for (int t = 0; t < 4; t++) {
            split2h(sc[2*t][0],   sc[2*t][1],   aPh[t][0], aPl[t][0]);
            split2h(sc[2*t][2],   sc[2*t][3],   aPh[t][1], aPl[t][1]);
            split2h(sc[2*t+1][0], sc[2*t+1][1], aPh[t][2], aPl[t][2]);
            split2h(sc[2*t+1][2], sc[2*t+1][3], aPh[t][3], aPl[t][3]);
        }
        // PV: exact P (hi+lo) x fp16 V = 128 mmas
        #pragma unroll
        for (int t = 0; t < 4; t++) {
            #pragma unroll
            for (int ng = 0; ng < 16; ng++) {
                uint32_t vf[2];
                LDS64(vf, vbase + (uint32_t)(((t * 16 + ng) * 32 + lane) * 8));
                mma_f16(o[ng], aPh[t], vf);
                mma_f16(o[ng], aPl[t], vf);
            }
        }
        MBAR_ARRIVE(AEMPTY(s));
        if (tid == 0 && kb + ASTAGES < niter) {
            int j = kb + ASTAGES;
            mbar_wait(AEMPTY(s), ph);
            MBAR_EXPECT_TX(AFULL(s), 32768);
            bulk_g2s(kbase, Kr + ((size_t)bhk * 32 + j) * 4096, 16384, AFULL(s));
            bulk_g2s(vbase, Vr + ((size_t)bhk * 32 + j) * 4096, 16384, AFULL(s));
        }
    }

    // epilogue: write WO-gemm A-fragments (bf16 hi/lo)
    float iA = 1.0f / lr0, iB = 1.0f / lr1;
    const int mt = b * 16 + qt;
    #pragma unroll
    for (int t = 0; t < 8; t++) {
        float o0 = o[2*t][0] * iA,   o1 = o[2*t][1] * iA;
        float o2 = o[2*t][2] * iB,   o3 = o[2*t][3] * iB;
        float o4 = o[2*t+1][0] * iA, o5 = o[2*t+1][1] * iA;
        float o6 = o[2*t+1][2] * iB, o7 = o[2*t+1][3] * iB;
        uint32_t h0,h1,h2,h3,l0,l1,l2,l3;
        split2(o0, o1, h0, l0);
        split2(o2, o3, h1, l1);
        split2(o4, o5, h2, l2);
        split2(o6, o7, h3, l3);
        int kglob = h * 128 + t * 16;
        int kc = kglob >> 5, ks2 = t & 1;
        uint4* tb = (uint4*)(Ap + ((size_t)mt * 64 + kc) * 4096);
        int bi = ((ks2 * 8 + wq) * 2) * 32 + lane;
        tb[bi]      = make_uint4(h0, h1, h2, h3);
        tb[bi + 32] = make_uint4(l0, l1, l2, l3);
    }
}

// ---------------- launcher ---------------------------------------------------
extern "C" void kernel_launch(void* const* d_in, const int* in_sizes, int n_in,
                              void* d_out, int out_size)
{
    const float* x    = (const float*)d_in[0];
    const float* fcos = (const float*)d_in[1];
    const float* fsin = (const float*)d_in[2];
    const float* wq   = (const float*)d_in[3];
    const float* wk   = (const float*)d_in[4];
    const float* wv   = (const float*)d_in[5];
    const float* wo   = (const float*)d_in[6];
    float* out = (float*)d_out;

    float *pxp, *pattp, *pwqkvp, *pwop, *pQr, *pKr, *pVr;
    cudaGetSymbolAddress((void**)&pxp, g_xp);
    cudaGetSymbolAddress((void**)&pattp, g_attp);
    cudaGetSymbolAddress((void**)&pwqkvp, g_wqkvp);
    cudaGetSymbolAddress((void**)&pwop, g_wop);
    cudaGetSymbolAddress((void**)&pQr, g_Qr);
    cudaGetSymbolAddress((void**)&pKr, g_Kr);
    cudaGetSymbolAddress((void**)&pVr, g_Vr);

    const size_t gsmem = GSTAGES * STAGE_BYTES + 1024;
    cudaFuncSetAttribute(gemm_mma<0>, cudaFuncAttributeMaxDynamicSharedMemorySize, (int)gsmem);
    cudaFuncSetAttribute(gemm_mma<1>, cudaFuncAttributeMaxDynamicSharedMemorySize, (int)gsmem);
    cudaFuncSetAttribute(attn_mma, cudaFuncAttributeMaxDynamicSharedMemorySize, ATTN_SMEM);

    // packs (bf16 hi/lo for GEMMs)
    pack_B_qkv<<<dim3(KTILES, 32), 256>>>(wq, wk, wv, pwqkvp);
    pack_B_bf16<<<dim3(KTILES, DIM/128), 256>>>(wo, pwop, DIM);
    pack_A_bf16<<<dim3(KTILES, M_ROWS/128), 256>>>(x, pxp, DIM);

    // fused QKV projection (bf16x3) + rope + fp16 fragment repack (epilogue)
    gemm_mma<1><<<dim3(CD/128, M_ROWS/128), 256, gsmem>>>(
        pxp, pwqkvp, nullptr, CD, KTILES, pQr, pKr, pVr, fcos, fsin);

    // tensor-core flash attention (fp16 QK, exactP-fp16V PV; writes WO A-frags)
    attn_mma<<<dim3(16, BB * NH), 256, ATTN_SMEM>>>(pQr, pKr, pVr, pattp);

    // output projection (bf16x3)
    gemm_mma<0><<<dim3(DIM/128, M_ROWS/128), 256, gsmem>>>(
        pattp, pwop, out, DIM, KTILES, nullptr, nullptr, nullptr, nullptr, nullptr);
}

// round 12
// speedup vs baseline: 1.2607x; 1.0965x over previous
#include <cuda_runtime.h>
#include <cuda_bf16.h>
#include <cuda_fp16.h>
#include <cstdint>

// Problem constants
#define BB 2
#define SS 2048
#define DIM 2048
#define NH 16
#define NKV 8
#define HD 128
#define M_ROWS (BB*SS)          // 4096
#define KTILES 64               // K=2048 / 32
#define CD 4096                 // fused QKV output width

// ---------------- scratch (device globals: allocation-free) ----------------
__device__ float g_xp   [(size_t)M_ROWS * DIM];       // A tiles (bf16 hi/lo)
__device__ float g_attp [(size_t)M_ROWS * DIM];       // A tiles (fp16 hi/lo)
__device__ float g_wqkvp[(size_t)DIM * CD];           // B tiles (bf16 hi/lo interleaved)
__device__ float g_wop  [(size_t)DIM * DIM / 2];      // B tiles (fp16 single)
// fragment-major tiles for attention (fp16)
__device__ float g_Qr[(size_t)BB * NH  * 32 * 4096];  // A-frags fp16 single (16KB/tile)
__device__ float g_Kr[(size_t)BB * NKV * 32 * 4096];  // B-frags fp16 single (16KB/tile)
__device__ float g_Vr[(size_t)BB * NKV * 32 * 4096];  // B-frags fp16 single (16KB/tile)

// ---------------- PTX helpers (base sm_90 / sm_80 features only!) -----------
__device__ __forceinline__ uint32_t smem_u32(const void* p) {
    uint32_t a;
    asm("{ .reg .u64 t; cvta.to.shared.u64 t, %1; cvt.u32.u64 %0, t; }" : "=r"(a) : "l"(p));
    return a;
}

#define MBAR_INIT(a, cnt) \
    asm volatile("mbarrier.init.shared.b64 [%0], %1;" :: "r"(a), "r"(cnt) : "memory")
#define MBAR_EXPECT_TX(a, b) \
    asm volatile("mbarrier.arrive.expect_tx.shared.b64 _, [%0], %1;" :: "r"(a), "r"(b) : "memory")
#define MBAR_ARRIVE(a) \
    asm volatile("mbarrier.arrive.shared.b64 _, [%0];" :: "r"(a) : "memory")

__device__ __forceinline__ void mbar_wait(uint32_t addr, uint32_t phase) {
    uint32_t done;
    asm volatile(
        "{\n\t.reg .pred p;\n\t"
        "mbarrier.try_wait.parity.acquire.cta.shared::cta.b64 p, [%1], %2;\n\t"
        "selp.b32 %0, 1, 0, p;\n\t}"
        : "=r"(done) : "r"(addr), "r"(phase) : "memory");
    if (!done) {
        asm volatile(
            "{\n\t.reg .pred P1;\n\t"
            "W_%=:\n\t"
            "mbarrier.try_wait.parity.acquire.cta.shared::cta.b64 P1, [%0], %1, 0x989680;\n\t"
            "@P1 bra.uni D_%=;\n\t"
            "bra.uni W_%=;\n\t"
            "D_%=:\n\t}"
            :: "r"(addr), "r"(phase) : "memory");
    }
}
__device__ __forceinline__ void bulk_g2s(uint32_t dst, const void* src, uint32_t bytes, uint32_t mbar) {
    asm volatile(
        "cp.async.bulk.shared::cluster.global.mbarrier::complete_tx::bytes [%0], [%1], %2, [%3];"
        :: "r"(dst), "l"(src), "r"(bytes), "r"(mbar) : "memory");
}
__device__ __forceinline__ void fence_async() {
    asm volatile("fence.proxy.async;" ::: "memory");
}

__device__ __forceinline__ void mma_bf16(float* c, const uint32_t* a, const uint32_t* b) {
    asm volatile(
        "mma.sync.aligned.m16n8k16.row.col.f32.bf16.bf16.f32 "
        "{%0,%1,%2,%3}, {%4,%5,%6,%7}, {%8,%9}, {%0,%1,%2,%3};"
        : "+f"(c[0]), "+f"(c[1]), "+f"(c[2]), "+f"(c[3])
        : "r"(a[0]), "r"(a[1]), "r"(a[2]), "r"(a[3]), "r"(b[0]), "r"(b[1]));
}
__device__ __forceinline__ void mma_f16(float* c, const uint32_t* a, const uint32_t* b) {
    asm volatile(
        "mma.sync.aligned.m16n8k16.row.col.f32.f16.f16.f32 "
        "{%0,%1,%2,%3}, {%4,%5,%6,%7}, {%8,%9}, {%0,%1,%2,%3};"
        : "+f"(c[0]), "+f"(c[1]), "+f"(c[2]), "+f"(c[3])
        : "r"(a[0]), "r"(a[1]), "r"(a[2]), "r"(a[3]), "r"(b[0]), "r"(b[1]));
}
#define LDS128(r, addr) \
    asm volatile("ld.shared.v4.b32 {%0,%1,%2,%3}, [%4];" \
        : "=r"((r)[0]), "=r"((r)[1]), "=r"((r)[2]), "=r"((r)[3]) : "r"(addr))
#define LDS64(r, addr) \
    asm volatile("ld.shared.v2.b32 {%0,%1}, [%2];" \
        : "=r"((r)[0]), "=r"((r)[1]) : "r"(addr))

// bf16 split: fp32 pair -> bf16-hi pair + bf16-lo (residual) pair
__device__ __forceinline__ void split2(float x, float y, uint32_t& h, uint32_t& l) {
    __nv_bfloat16 hx = __float2bfloat16_rn(x);
    __nv_bfloat16 hy = __float2bfloat16_rn(y);
    float lx = x - __bfloat162float(hx);
    float ly = y - __bfloat162float(hy);
    __nv_bfloat162 hp = __halves2bfloat162(hx, hy);
    __nv_bfloat162 lp = __floats2bfloat162_rn(lx, ly);
    h = *reinterpret_cast<uint32_t*>(&hp);
    l = *reinterpret_cast<uint32_t*>(&lp);
}
// fp16 split / pack
__device__ __forceinline__ void split2h(float x, float y, uint32_t& h, uint32_t& l) {
    __half hx = __float2half_rn(x);
    __half hy = __float2half_rn(y);
    float lx = x - __half2float(hx);
    float ly = y - __half2float(hy);
    __half2 hp = __halves2half2(hx, hy);
    __half2 lp = __floats2half2_rn(lx, ly);
    h = *reinterpret_cast<uint32_t*>(&hp);
    l = *reinterpret_cast<uint32_t*>(&lp);
}
__device__ __forceinline__ uint32_t packh(float x, float y) {
    __half2 hp = __floats2half2_rn(x, y);
    return *reinterpret_cast<uint32_t*>(&hp);
}

// ---------------- pack A (smem-staged): [M,K] -> bf16 hi/lo A-frag tiles -----
__global__ __launch_bounds__(256) void pack_A_bf16(const float* __restrict__ src,
                                                   float* __restrict__ dst, int K)
{
    __shared__ float sa[128][33];
    const int kc = blockIdx.x, mt = blockIdx.y;
    const int tid = threadIdx.x;
    #pragma unroll
    for (int t = 0; t < 4; t++) {
        int u = tid + 256 * t;
        int r = u >> 3, c4 = u & 7;
        float4 v = *(const float4*)(src + (size_t)(mt * 128 + r) * K + kc * 32 + c4 * 4);
        sa[r][c4 * 4 + 0] = v.x; sa[r][c4 * 4 + 1] = v.y;
        sa[r][c4 * 4 + 2] = v.z; sa[r][c4 * 4 + 3] = v.w;
    }
    __syncthreads();
    uint4* tb = (uint4*)(dst + (size_t)(mt * (K / 32) + kc) * 4096);
    #pragma unroll
    for (int t = 0; t < 2; t++) {
        int u = tid + 256 * t;
        int ks2 = u >> 8, mtg = (u >> 5) & 7, lane = u & 31;
        int ml = mtg * 16 + (lane >> 2);
        int kl = ks2 * 16 + (lane & 3) * 2;
        uint32_t h0,h1,h2,h3,l0,l1,l2,l3;
        split2(sa[ml][kl],         sa[ml][kl + 1],       h0, l0);
        split2(sa[ml + 8][kl],     sa[ml + 8][kl + 1],   h1, l1);
        split2(sa[ml][kl + 8],     sa[ml][kl + 9],       h2, l2);
        split2(sa[ml + 8][kl + 8], sa[ml + 8][kl + 9],   h3, l3);
        int bi = ((ks2 * 8 + mtg) * 2) * 32 + lane;
        tb[bi]      = make_uint4(h0, h1, h2, h3);
        tb[bi + 32] = make_uint4(l0, l1, l2, l3);
    }
}

// ---------------- pack B bf16 hi/lo interleaved (16KB tiles) ------------------
__device__ __forceinline__ void pack_B_body(const float* __restrict__ w, int N,
                                            int kc, int ntl, uint4* __restrict__ tb)
{
    __shared__ float sb[32][129];
    const int tid = threadIdx.x;
    #pragma unroll
    for (int t = 0; t < 4; t++) {
        int u = tid + 256 * t;
        int r = u >> 5, c4 = u & 31;
        float4 v = *(const float4*)(w + (size_t)(kc * 32 + r) * N + ntl * 128 + c4 * 4);
        sb[r][c4 * 4 + 0] = v.x; sb[r][c4 * 4 + 1] = v.y;
        sb[r][c4 * 4 + 2] = v.z; sb[r][c4 * 4 + 3] = v.w;
    }
    __syncthreads();
    #pragma unroll
    for (int t = 0; t < 4; t++) {
        int u = tid + 256 * t;
        int ks2 = u >> 9, ntg = (u >> 5) & 15, lane = u & 31;
        int kl = ks2 * 16 + (lane & 3) * 2;
        int nl = ntg * 8 + (lane >> 2);
        uint32_t bh0, bl0, bh1, bl1;
        split2(sb[kl][nl],     sb[kl + 1][nl], bh0, bl0);
        split2(sb[kl + 8][nl], sb[kl + 9][nl], bh1, bl1);
        tb[(ks2 * 16 + ntg) * 32 + lane] = make_uint4(bh0, bh1, bl0, bl1);
    }
}

__global__ __launch_bounds__(256) void pack_B_qkv(const float* __restrict__ wq,
                                                  const float* __restrict__ wk,
                                                  const float* __restrict__ wv,
                                                  float* __restrict__ dst)
{
    const int kc = blockIdx.x, nt = blockIdx.y;
    uint4* tb = (uint4*)(dst + (size_t)(nt * KTILES + kc) * 4096);
    if (nt < 16)      pack_B_body(wq, DIM,    kc, nt,      tb);
    else if (nt < 24) pack_B_body(wk, NKV*HD, kc, nt - 16, tb);
    else              pack_B_body(wv, NKV*HD, kc, nt - 24, tb);
}

// ---------------- pack B fp16 single (8KB tiles) for WO -----------------------
__global__ __launch_bounds__(256) void pack_B_f16(const float* __restrict__ w,
                                                  float* __restrict__ dst, int N)
{
    __shared__ float sb[32][129];
    const int kc = blockIdx.x, nt = blockIdx.y;
    const int tid = threadIdx.x;
    #pragma unroll
    for (int t = 0; t < 4; t++) {
        int u = tid + 256 * t;
        int r = u >> 5, c4 = u & 31;
        float4 v = *(const float4*)(w + (size_t)(kc * 32 + r) * N + nt * 128 + c4 * 4);
        sb[r][c4 * 4 + 0] = v.x; sb[r][c4 * 4 + 1] = v.y;
        sb[r][c4 * 4 + 2] = v.z; sb[r][c4 * 4 + 3] = v.w;
    }
    __syncthreads();
    uint2* tb = (uint2*)(dst + (size_t)(nt * KTILES + kc) * 2048);
    #pragma unroll
    for (int t = 0; t < 4; t++) {
        int u = tid + 256 * t;
        int ks2 = u >> 9, ntg = (u >> 5) & 15, lane = u & 31;
        int kl = ks2 * 16 + (lane & 3) * 2;
        int nl = ntg * 8 + (lane >> 2);
        uint32_t bh0 = packh(sb[kl][nl],     sb[kl + 1][nl]);
        uint32_t bh1 = packh(sb[kl + 8][nl], sb[kl + 9][nl]);
        tb[(ks2 * 16 + ntg) * 32 + lane] = make_uint2(bh0, bh1);
    }
}

// ---------------- rope from smem tile ----------------------------------------
#define CPIT 132
__device__ __forceinline__ float rope_s(const float* __restrict__ scs, int row, int hd,
                                        const float* __restrict__ cosp,
                                        const float* __restrict__ sinp, int srow)
{
    int j = hd >> 1;
    float c = cosp[srow * 64 + j];
    float s = sinp[srow * 64 + j];
    float v0 = scs[row * CPIT + (hd & ~1)];
    float v1 = scs[row * CPIT + (hd | 1)];
    return (hd & 1) ? (v0 * s + v1 * c) : (v0 * c - v1 * s);
}

// ---------------- bf16x3 GEMM (QKV): fused rope + fp16-frag epilogue ---------
#define GSTAGES 3
#define STAGE_BYTES 32768

__global__ __launch_bounds__(256, 2) void gemm_qkv(
    const float* __restrict__ Ap, const float* __restrict__ Bp,
    int kTiles,
    float* __restrict__ Qr, float* __restrict__ Kr, float* __restrict__ Vr,
    const float* __restrict__ cosp, const float* __restrict__ sinp)
{
    extern __shared__ float dyn[];
    __shared__ __align__(8) uint64_t mbar[2 * GSTAGES];

    const int tid  = threadIdx.x;
    const int lane = tid & 31;
    const int warp = tid >> 5;
    const int wm = warp >> 2;
    const int wn = warp & 3;
    const int nt = blockIdx.x, mt = blockIdx.y;

    uint32_t sbase = (smem_u32(dyn) + 1023) & ~1023u;
    uint32_t mb = smem_u32(mbar);
    #define FULLB(s)  (mb + (s) * 8)
    #define EMPTYB(s) (mb + (GSTAGES + (s)) * 8)

    if (tid == 0) {
        #pragma unroll
        for (int s = 0; s < GSTAGES; s++) {
            MBAR_INIT(FULLB(s), 1);
            MBAR_INIT(EMPTYB(s), 256);
        }
    }
    __syncthreads();

    const char* At = (const char*)(Ap + (size_t)mt * kTiles * 4096);
    const char* Bt = (const char*)(Bp + (size_t)nt * kTiles * 4096);

    if (tid == 0) {
        fence_async();
        #pragma unroll
        for (int j = 0; j < GSTAGES; j++) {
            MBAR_EXPECT_TX(FULLB(j), STAGE_BYTES);
            bulk_g2s(sbase + j * STAGE_BYTES,         At + (size_t)j * 16384, 16384, FULLB(j));
            bulk_g2s(sbase + j * STAGE_BYTES + 16384, Bt + (size_t)j * 16384, 16384, FULLB(j));
        }
    }

    float acc[4][4][4];
    #pragma unroll
    for (int i = 0; i < 4; i++)
        #pragma unroll
        for (int j = 0; j < 4; j++)
            #pragma unroll
            for (int q = 0; q < 4; q++) acc[i][j][q] = 0.f;

    for (int i = 0; i < kTiles; i++) {
        const int s = i % GSTAGES;
        const uint32_t ph = (i / GSTAGES) & 1;
        mbar_wait(FULLB(s), ph);
        const uint32_t a_base = sbase + s * STAGE_BYTES;
        const uint32_t b_base = a_base + 16384;

        #pragma unroll
        for (int ks = 0; ks < 2; ks++) {
            uint32_t ah[4][4], al[4][4], bf[4][4];
            #pragma unroll
            for (int ii = 0; ii < 4; ii++) {
                LDS128(ah[ii], a_base + (uint32_t)((((ks * 8 + wm * 4 + ii) * 2 + 0) * 32 + lane) * 16));
                LDS128(al[ii], a_base + (uint32_t)((((ks * 8 + wm * 4 + ii) * 2 + 1) * 32 + lane) * 16));
            }
            #pragma unroll
            for (int jj = 0; jj < 4; jj++)
                LDS128(bf[jj], b_base + (uint32_t)(((ks * 16 + wn * 4 + jj) * 32 + lane) * 16));
            #pragma unroll
            for (int ii = 0; ii < 4; ii++)
                #pragma unroll
                for (int jj = 0; jj < 4; jj++) {
                    mma_bf16(acc[ii][jj], ah[ii], &bf[jj][0]);
                    mma_bf16(acc[ii][jj], ah[ii], &bf[jj][2]);
                    mma_bf16(acc[ii][jj], al[ii], &bf[jj][0]);
                }
        }
        MBAR_ARRIVE(EMPTYB(s));
        if (tid == 0) {
            int jn = i + GSTAGES;
            if (jn < kTiles) {
                mbar_wait(EMPTYB(s), ph);
                MBAR_EXPECT_TX(FULLB(s), STAGE_BYTES);
                bulk_g2s(a_base, At + (size_t)jn * 16384, 16384, FULLB(s));
                bulk_g2s(b_base, Bt + (size_t)jn * 16384, 16384, FULLB(s));
            }
        }
    }

    const int r = lane >> 2, cc = lane & 3;

    // fused QKV epilogue (Q/K/V -> fp16 frag tiles)
    __syncthreads();
    float* scs = dyn;
    #pragma unroll
    for (int ii = 0; ii < 4; ii++) {
        int rl = wm * 64 + ii * 16 + r;
        int cl = wn * 32 + 2 * cc;
        #pragma unroll
        for (int jj = 0; jj < 4; jj++) {
            *(float2*)&scs[rl * CPIT + cl + jj * 8]       = make_float2(acc[ii][jj][0], acc[ii][jj][1]);
            *(float2*)&scs[(rl + 8) * CPIT + cl + jj * 8] = make_float2(acc[ii][jj][2], acc[ii][jj][3]);
        }
    }
    __syncthreads();

    const int b = mt >> 4;
    const int row_base = mt * 128;

    if (nt < 16) {
        const float scale = 0.08838834764831845f;
        const int bh = b * 16 + nt;
        #pragma unroll
        for (int qhalf = 0; qhalf < 2; qhalf++) {
            uint4* out = (uint4*)(Qr + ((size_t)bh * 32 + (mt & 15) * 2 + qhalf) * 4096);
            #pragma unroll
            for (int t = 0; t < 4; t++) {
                int u = tid + 256 * t;
                int mtg = u >> 8, ds = (u >> 5) & 7, l2 = u & 31;
                int rl = qhalf * 64 + mtg * 16 + (l2 >> 2);
                int k  = ds * 16 + (l2 & 3) * 2;
                int s0 = (row_base + rl) & (SS - 1);
                int s1 = (row_base + rl + 8) & (SS - 1);
                uint32_t h0 = packh(rope_s(scs, rl,     k,     cosp, sinp, s0) * scale,
                                    rope_s(scs, rl,     k + 1, cosp, sinp, s0) * scale);
                uint32_t h1 = packh(rope_s(scs, rl + 8, k,     cosp, sinp, s1) * scale,
                                    rope_s(scs, rl + 8, k + 1, cosp, sinp, s1) * scale);
                uint32_t h2 = packh(rope_s(scs, rl,     k + 8, cosp, sinp, s0) * scale,
                                    rope_s(scs, rl,     k + 9, cosp, sinp, s0) * scale);
                uint32_t h3 = packh(rope_s(scs, rl + 8, k + 8, cosp, sinp, s1) * scale,
                                    rope_s(scs, rl + 8, k + 9, cosp, sinp, s1) * scale);
                out[(mtg * 8 + ds) * 32 + l2] = make_uint4(h0, h1, h2, h3);
            }
        }
    } else if (nt < 24) {
        const int bhk = b * 8 + (nt - 16);
        #pragma unroll
        for (int kvhalf = 0; kvhalf < 2; kvhalf++) {
            uint2* out = (uint2*)(Kr + ((size_t)bhk * 32 + (mt & 15) * 2 + kvhalf) * 4096);
            #pragma unroll
            for (int t = 0; t < 8; t++) {
                int u = tid + 256 * t;
                int ds = u >> 8, kvg = (u >> 5) & 7, l2 = u & 31;
                int rl = kvhalf * 64 + kvg * 8 + (l2 >> 2);
                int d  = ds * 16 + (l2 & 3) * 2;
                int srow = (row_base + rl) & (SS - 1);
                uint32_t kh0 = packh(rope_s(scs, rl, d,     cosp, sinp, srow),
                                     rope_s(scs, rl, d + 1, cosp, sinp, srow));
                uint32_t kh1 = packh(rope_s(scs, rl, d + 8, cosp, sinp, srow),
                                     rope_s(scs, rl, d + 9, cosp, sinp, srow));
                out[(ds * 8 + kvg) * 32 + l2] = make_uint2(kh0, kh1);
            }
        }
    } else {
        const int bhk = b * 8 + (nt - 24);
        #pragma unroll
        for (int vhalf = 0; vhalf < 2; vhalf++) {
            uint2* out = (uint2*)(Vr + ((size_t)bhk * 32 + (mt & 15) * 2 + vhalf) * 4096);
            #pragma unroll
            for (int it = 0; it < 8; it++) {
                int u = tid + 256 * it;
                int l2 = u & 31, ng = (u >> 5) & 15, ks = u >> 9;
                int kv0 = vhalf * 64 + ks * 16 + (l2 & 3) * 2;
                int d   = ng * 8 + (l2 >> 2);
                uint32_t vh0 = packh(scs[kv0 * CPIT + d],       scs[(kv0 + 1) * CPIT + d]);
                uint32_t vh1 = packh(scs[(kv0 + 8) * CPIT + d], scs[(kv0 + 9) * CPIT + d]);
                out[(ks * 16 + ng) * 32 + l2] = make_uint2(vh0, vh1);
            }
        }
    }
}

// ---------------- fp16x2 GEMM (WO): A exact fp16 hi/lo, B single fp16 --------
#define WSTAGES 4
#define WSTAGE_BYTES 24576      // A 16KB + B 8KB

__global__ __launch_bounds__(256, 2) void gemm_wo(
    const float* __restrict__ Ap, const float* __restrict__ Bp,
    float* __restrict__ C, int Ndim, int kTiles)
{
    extern __shared__ float dyn[];
    __shared__ __align__(8) uint64_t mbar[2 * WSTAGES];

    const int tid  = threadIdx.x;
    const int lane = tid & 31;
    const int warp = tid >> 5;
    const int wm = warp >> 2;
    const int wn = warp & 3;
    const int nt = blockIdx.x, mt = blockIdx.y;

    uint32_t sbase = (smem_u32(dyn) + 1023) & ~1023u;
    uint32_t mb = smem_u32(mbar);
    #define WFULL(s)  (mb + (s) * 8)
    #define WEMPTY(s) (mb + (WSTAGES + (s)) * 8)

    if (tid == 0) {
        #pragma unroll
        for (int s = 0; s < WSTAGES; s++) {
            MBAR_INIT(WFULL(s), 1);
            MBAR_INIT(WEMPTY(s), 256);
        }
    }
    __syncthreads();

    const char* At = (const char*)(Ap + (size_t)mt * kTiles * 4096);
    const char* Bt = (const char*)(Bp + (size_t)nt * kTiles * 2048);

    if (tid == 0) {
        fence_async();
        #pragma unroll
        for (int j = 0; j < WSTAGES; j++) {
            MBAR_EXPECT_TX(WFULL(j), WSTAGE_BYTES);
            bulk_g2s(sbase + j * WSTAGE_BYTES,         At + (size_t)j * 16384, 16384, WFULL(j));
            bulk_g2s(sbase + j * WSTAGE_BYTES + 16384, Bt + (size_t)j * 8192,  8192,  WFULL(j));
        }
    }

    float acc[4][4][4];
    #pragma unroll
    for (int i = 0; i < 4; i++)
        #pragma unroll
        for (int j = 0; j < 4; j++)
            #pragma unroll
            for (int q = 0; q < 4; q++) acc[i][j][q] = 0.f;

    for (int i = 0; i < kTiles; i++) {
        const int s = i % WSTAGES;
        const uint32_t ph = (i / WSTAGES) & 1;
        mbar_wait(WFULL(s), ph);
        const uint32_t a_base = sbase + s * WSTAGE_BYTES;
        const uint32_t b_base = a_base + 16384;

        #pragma unroll
        for (int ks = 0; ks < 2; ks++) {
            uint32_t ah[4][4], al[4][4], bh[4][2];
            #pragma unroll
            for (int ii = 0; ii < 4; ii++) {
                LDS128(ah[ii], a_base + (uint32_t)((((ks * 8 + wm * 4 + ii) * 2 + 0) * 32 + lane) * 16));
                LDS128(al[ii], a_base + (uint32_t)((((ks * 8 + wm * 4 + ii) * 2 + 1) * 32 + lane) * 16));
            }
            #pragma unroll
            for (int jj = 0; jj < 4; jj++)
                LDS64(bh[jj], b_base + (uint32_t)(((ks * 16 + wn * 4 + jj) * 32 + lane) * 8));
            #pragma unroll
            for (int ii = 0; ii < 4; ii++)
                #pragma unroll
                for (int jj = 0; jj < 4; jj++) {
                    mma_f16(acc[ii][jj], ah[ii], bh[jj]);
                    mma_f16(acc[ii][jj], al[ii], bh[jj]);
                }
        }
        MBAR_ARRIVE(WEMPTY(s));
        if (tid == 0) {
            int jn = i + WSTAGES;
            if (jn < kTiles) {
                mbar_wait(WEMPTY(s), ph);
                MBAR_EXPECT_TX(WFULL(s), WSTAGE_BYTES);
                bulk_g2s(a_base, At + (size_t)jn * 16384, 16384, WFULL(s));
                bulk_g2s(b_base, Bt + (size_t)jn * 8192,  8192,  WFULL(s));
            }
        }
    }

    const int r = lane >> 2, cc = lane & 3;
    #pragma unroll
    for (int ii = 0; ii < 4; ii++) {
        int m0 = mt * 128 + wm * 64 + ii * 16 + r;
        float* row0 = C + (size_t)m0 * Ndim + nt * 128 + wn * 32 + 2 * cc;
        float* row1 = row0 + 8 * (size_t)Ndim;
        #pragma unroll
        for (int jj = 0; jj < 4; jj++) {
            *(float2*)(row0 + jj * 8) = make_float2(acc[ii][jj][0], acc[ii][jj][1]);
            *(float2*)(row1 + jj * 8) = make_float2(acc[ii][jj][2], acc[ii][jj][3]);
        }
    }
}

// ---------------- tensor-core flash attention (fp16 QK + exactP-fp16V PV) ----
// BQ=128 (8 warps), BKV=64, 3-stage ring (K 16KB + V 16KB per stage) = 96KB.
#define ASTAGES 3
#define ATTN_SMEM (ASTAGES * 32768)

__global__ __launch_bounds__(256) void attn_mma(
    const float* __restrict__ Qr, const float* __restrict__ Kr,
    const float* __restrict__ Vr, float* __restrict__ Ap)
{
    extern __shared__ float sm[];
    __shared__ __align__(8) uint64_t bars[2 * ASTAGES];

    const int tid = threadIdx.x;
    const int lane = tid & 31, wq = tid >> 5;
    const int qt = 15 - blockIdx.x;                  // heavy CTAs first
    const int bh = blockIdx.y;
    const int b = bh >> 4, h = bh & 15;
    const int bhk = b * 8 + (h >> 1);
    const int niter = 2 * qt + 2;

    uint32_t sbase = smem_u32(sm);
    uint32_t mb = smem_u32(bars);
    #define AFULL(s)  (mb + (s) * 8)
    #define AEMPTY(s) (mb + (ASTAGES + (s)) * 8)

    uint32_t qf[8][4];
    {
        const uint4* qsrc = (const uint4*)(Qr + ((size_t)bh * 32 + qt * 2 + (wq >> 2)) * 4096);
        const int mtg = wq & 3;
        #pragma unroll
        for (int ds = 0; ds < 8; ds++) {
            uint4 v = __ldg(&qsrc[(mtg * 8 + ds) * 32 + lane]);
            qf[ds][0] = v.x; qf[ds][1] = v.y; qf[ds][2] = v.z; qf[ds][3] = v.w;
        }
    }

    if (tid == 0) {
        #pragma unroll
        for (int s = 0; s < ASTAGES; s++) {
            MBAR_INIT(AFULL(s), 1);
            MBAR_INIT(AEMPTY(s), 256);
        }
    }
    __syncthreads();
    if (tid == 0) {
        fence_async();
        int np = niter < ASTAGES ? niter : ASTAGES;
        for (int j = 0; j < np; j++) {
            MBAR_EXPECT_TX(AFULL(j), 32768);
            bulk_g2s(sbase + j * 32768,         Kr + ((size_t)bhk * 32 + j) * 4096, 16384, AFULL(j));
            bulk_g2s(sbase + j * 32768 + 16384, Vr + ((size_t)bhk * 32 + j) * 4096, 16384, AFULL(j));
        }
    }

    float o[16][4];
    #pragma unroll
    for (int i = 0; i < 16; i++)
        #pragma unroll
        for (int q = 0; q < 4; q++) o[i][q] = 0.f;
    float mr0 = -1e30f, mr1 = -1e30f, lr0 = 0.f, lr1 = 0.f;
    const int r0 = lane >> 2;
    const int c0 = (lane & 3) * 2;
    const int qrow = qt * 128 + wq * 16 + r0;

    for (int kb = 0; kb < niter; kb++) {
        const int s = kb % ASTAGES;
        const uint32_t ph = (kb / ASTAGES) & 1;
        mbar_wait(AFULL(s), ph);
        const uint32_t kbase = sbase + s * 32768;
        const uint32_t vbase = kbase + 16384;

        float sc[8][4];
        #pragma unroll
        for (int ng = 0; ng < 8; ng++)
            #pragma unroll
            for (int q = 0; q < 4; q++) sc[ng][q] = 0.f;
        #pragma unroll
        for (int ds = 0; ds < 8; ds++) {
            #pragma unroll
            for (int ng = 0; ng < 8; ng++) {
                uint32_t kf[2];
                LDS64(kf, kbase + (uint32_t)(((ds * 8 + ng) * 32 + lane) * 8));
                mma_f16(sc[ng], qf[ds], kf);
            }
        }
        if (kb >= 2 * qt) {
            #pragma unroll
            for (int ng = 0; ng < 8; ng++) {
                int col = kb * 64 + ng * 8 + c0;
                if (col     > qrow)     sc[ng][0] = -1e30f;
                if (col + 1 > qrow)     sc[ng][1] = -1e30f;
                if (col     > qrow + 8) sc[ng][2] = -1e30f;
                if (col + 1 > qrow + 8) sc[ng][3] = -1e30f;
            }
        }
        float mA = -1e30f, mB = -1e30f;
        #pragma unroll
        for (int ng = 0; ng < 8; ng++) {
            mA = fmaxf(mA, fmaxf(sc[ng][0], sc[ng][1]));
            mB = fmaxf(mB, fmaxf(sc[ng][2], sc[ng][3]));
        }
        mA = fmaxf(mA, __shfl_xor_sync(0xffffffffu, mA, 1));
        mA = fmaxf(mA, __shfl_xor_sync(0xffffffffu, mA, 2));
        mB = fmaxf(mB, __shfl_xor_sync(0xffffffffu, mB, 1));
        mB = fmaxf(mB, __shfl_xor_sync(0xffffffffu, mB, 2));
        float mnA = fmaxf(mr0, mA), mnB = fmaxf(mr1, mB);
        float fA = __expf(mr0 - mnA), fB = __expf(mr1 - mnB);
        mr0 = mnA; mr1 = mnB;
        float sA = 0.f, sB = 0.f;
        #pragma unroll
        for (int ng = 0; ng < 8; ng++) {
            sc[ng][0] = __expf(sc[ng][0] - mnA);
            sc[ng][1] = __expf(sc[ng][1] - mnA);
            sc[ng][2] = __expf(sc[ng][2] - mnB);
            sc[ng][3] = __expf(sc[ng][3] - mnB);
            sA += sc[ng][0] + sc[ng][1];
            sB += sc[ng][2] + sc[ng][3];
        }
        sA += __shfl_xor_sync(0xffffffffu, sA, 1);
        sA += __shfl_xor_sync(0xffffffffu, sA, 2);
        sB += __shfl_xor_sync(0xffffffffu, sB, 1);
        sB += __shfl_xor_sync(0xffffffffu, sB, 2);
        lr0 = lr0 * fA + sA;
        lr1 = lr1 * fB + sB;
        #pragma unroll
        for (int ng = 0; ng < 16; ng++) {
            o[ng][0] *= fA; o[ng][1] *= fA;
            o[ng][2] *= fB; o[ng][3] *= fB;
        }
        uint32_t aPh[4][4], aPl[4][4];
        #pragma unroll
        for (int t = 0; t < 4; t++) {
            split2h(sc[2*t][0],   sc[2*t][1],   aPh[t][0], aPl[t][0]);
            split2h(sc[2*t][2],   sc[2*t][3],   aPh[t][1], aPl[t][1]);
            split2h(sc[2*t+1][0], sc[2*t+1][1], aPh[t][2], aPl[t][2]);
            split2h(sc[2*t+1][2], sc[2*t+1][3], aPh[t][3], aPl[t][3]);
        }
        #pragma unroll
        for (int t = 0; t < 4; t++) {
            #pragma unroll
            for (int ng = 0; ng < 16; ng++) {
                uint32_t vf[2];
                LDS64(vf, vbase + (uint32_t)(((t * 16 + ng) * 32 + lane) * 8));
                mma_f16(o[ng], aPh[t], vf);
                mma_f16(o[ng], aPl[t], vf);
            }
        }
        MBAR_ARRIVE(AEMPTY(s));
        if (tid == 0 && kb + ASTAGES < niter) {
            int j = kb + ASTAGES;
            mbar_wait(AEMPTY(s), ph);
            MBAR_EXPECT_TX(AFULL(s), 32768);
            bulk_g2s(kbase, Kr + ((size_t)bhk * 32 + j) * 4096, 16384, AFULL(s));
            bulk_g2s(vbase, Vr + ((size_t)bhk * 32 + j) * 4096, 16384, AFULL(s));
        }
    }

    // epilogue: write WO-gemm A-fragments (fp16 hi/lo — exact)
    float iA = 1.0f / lr0, iB = 1.0f / lr1;
    const int mt = b * 16 + qt;
    #pragma unroll
    for (int t = 0; t < 8; t++) {
        float o0 = o[2*t][0] * iA,   o1 = o[2*t][1] * iA;
        float o2 = o[2*t][2] * iB,   o3 = o[2*t][3] * iB;
        float o4 = o[2*t+1][0] * iA, o5 = o[2*t+1][1] * iA;
        float o6 = o[2*t+1][2] * iB, o7 = o[2*t+1][3] * iB;
        uint32_t h0,h1,h2,h3,l0,l1,l2,l3;
        split2h(o0, o1, h0, l0);
        split2h(o2, o3, h1, l1);
        split2h(o4, o5, h2, l2);
        split2h(o6, o7, h3, l3);
        int kglob = h * 128 + t * 16;
        int kc = kglob >> 5, ks2 = t & 1;
        uint4* tb = (uint4*)(Ap + ((size_t)mt * 64 + kc) * 4096);
        int bi = ((ks2 * 8 + wq) * 2) * 32 + lane;
        tb[bi]      = make_uint4(h0, h1, h2, h3);
        tb[bi + 32] = make_uint4(l0, l1, l2, l3);
    }
}

// ---------------- launcher ---------------------------------------------------
extern "C" void kernel_launch(void* const* d_in, const int* in_sizes, int n_in,
                              void* d_out, int out_size)
{
    const float* x    = (const float*)d_in[0];
    const float* fcos = (const float*)d_in[1];
    const float* fsin = (const float*)d_in[2];
    const float* wq   = (const float*)d_in[3];
    const float* wk   = (const float*)d_in[4];
    const float* wv   = (const float*)d_in[5];
    const float* wo   = (const float*)d_in[6];
    float* out = (float*)d_out;

    float *pxp, *pattp, *pwqkvp, *pwop, *pQr, *pKr, *pVr;
    cudaGetSymbolAddress((void**)&pxp, g_xp);
    cudaGetSymbolAddress((void**)&pattp, g_attp);
    cudaGetSymbolAddress((void**)&pwqkvp, g_wqkvp);
    cudaGetSymbolAddress((void**)&pwop, g_wop);
    cudaGetSymbolAddress((void**)&pQr, g_Qr);
    cudaGetSymbolAddress((void**)&pKr, g_Kr);
    cudaGetSymbolAddress((void**)&pVr, g_Vr);

    const size_t gsmem = GSTAGES * STAGE_BYTES + 1024;
    const size_t wsmem = WSTAGES * WSTAGE_BYTES + 1024;
    cudaFuncSetAttribute(gemm_qkv, cudaFuncAttributeMaxDynamicSharedMemorySize, (int)gsmem);
    cudaFuncSetAttribute(gemm_wo,  cudaFuncAttributeMaxDynamicSharedMemorySize, (int)wsmem);
    cudaFuncSetAttribute(attn_mma, cudaFuncAttributeMaxDynamicSharedMemorySize, ATTN_SMEM);

    // packs
    pack_B_qkv<<<dim3(KTILES, 32), 256>>>(wq, wk, wv, pwqkvp);
    pack_B_f16<<<dim3(KTILES, DIM/128), 256>>>(wo, pwop, DIM);
    pack_A_bf16<<<dim3(KTILES, M_ROWS/128), 256>>>(x, pxp, DIM);

    // fused QKV projection (bf16x3) + rope + fp16 fragment repack (epilogue)
    gemm_qkv<<<dim3(CD/128, M_ROWS/128), 256, gsmem>>>(
        pxp, pwqkvp, KTILES, pQr, pKr, pVr, fcos, fsin);

    // tensor-core flash attention (fp16 QK, exactP-fp16V PV; writes WO A-frags)
    attn_mma<<<dim3(16, BB * NH), 256, ATTN_SMEM>>>(pQr, pKr, pVr, pattp);

    // output projection (fp16x2: exact A, fp16 B)
    gemm_wo<<<dim3(DIM/128, M_ROWS/128), 256, wsmem>>>(pattp, pwop, out, DIM, KTILES);
}

// round 13
// speedup vs baseline: 1.4785x; 1.1728x over previous
#include <cuda_runtime.h>
#include <cuda_bf16.h>
#include <cuda_fp16.h>
#include <cstdint>

// Problem constants
#define BB 2
#define SS 2048
#define DIM 2048
#define NH 16
#define NKV 8
#define HD 128
#define M_ROWS (BB*SS)          // 4096
#define KTILES 64               // K=2048 / 32
#define CD 4096                 // fused QKV output width

// ---------------- scratch (device globals: allocation-free) ----------------
__device__ float g_xp   [(size_t)M_ROWS * DIM];       // A tiles (bf16 hi/lo)
__device__ float g_attp [(size_t)M_ROWS * DIM / 2];   // A tiles (fp16 single)
__device__ float g_wqkvp[(size_t)DIM * CD];           // B tiles (bf16 hi/lo interleaved)
__device__ float g_wop  [(size_t)DIM * DIM / 2];      // B tiles (fp16 single)
// fragment-major tiles for attention (fp16)
__device__ float g_Qr[(size_t)BB * NH  * 32 * 4096];  // A-frags fp16 single (16KB/tile)
__device__ float g_Kr[(size_t)BB * NKV * 32 * 4096];  // B-frags fp16 single (16KB/tile)
__device__ float g_Vr[(size_t)BB * NKV * 32 * 4096];  // B-frags fp16 single (16KB/tile)

// ---------------- PTX helpers (base sm_90 / sm_80 features only!) -----------
__device__ __forceinline__ uint32_t smem_u32(const void* p) {
    uint32_t a;
    asm("{ .reg .u64 t; cvta.to.shared.u64 t, %1; cvt.u32.u64 %0, t; }" : "=r"(a) : "l"(p));
    return a;
}

#define MBAR_INIT(a, cnt) \
    asm volatile("mbarrier.init.shared.b64 [%0], %1;" :: "r"(a), "r"(cnt) : "memory")
#define MBAR_EXPECT_TX(a, b) \
    asm volatile("mbarrier.arrive.expect_tx.shared.b64 _, [%0], %1;" :: "r"(a), "r"(b) : "memory")
#define MBAR_ARRIVE(a) \
    asm volatile("mbarrier.arrive.shared.b64 _, [%0];" :: "r"(a) : "memory")

__device__ __forceinline__ void mbar_wait(uint32_t addr, uint32_t phase) {
    uint32_t done;
    asm volatile(
        "{\n\t.reg .pred p;\n\t"
        "mbarrier.try_wait.parity.acquire.cta.shared::cta.b64 p, [%1], %2;\n\t"
        "selp.b32 %0, 1, 0, p;\n\t}"
        : "=r"(done) : "r"(addr), "r"(phase) : "memory");
    if (!done) {
        asm volatile(
            "{\n\t.reg .pred P1;\n\t"
            "W_%=:\n\t"
            "mbarrier.try_wait.parity.acquire.cta.shared::cta.b64 P1, [%0], %1, 0x989680;\n\t"
            "@P1 bra.uni D_%=;\n\t"
            "bra.uni W_%=;\n\t"
            "D_%=:\n\t}"
            :: "r"(addr), "r"(phase) : "memory");
    }
}
__device__ __forceinline__ void bulk_g2s(uint32_t dst, const void* src, uint32_t bytes, uint32_t mbar) {
    asm volatile(
        "cp.async.bulk.shared::cluster.global.mbarrier::complete_tx::bytes [%0], [%1], %2, [%3];"
        :: "r"(dst), "l"(src), "r"(bytes), "r"(mbar) : "memory");
}
__device__ __forceinline__ void fence_async() {
    asm volatile("fence.proxy.async;" ::: "memory");
}

__device__ __forceinline__ void mma_bf16(float* c, const uint32_t* a, const uint32_t* b) {
    asm volatile(
        "mma.sync.aligned.m16n8k16.row.col.f32.bf16.bf16.f32 "
        "{%0,%1,%2,%3}, {%4,%5,%6,%7}, {%8,%9}, {%0,%1,%2,%3};"
        : "+f"(c[0]), "+f"(c[1]), "+f"(c[2]), "+f"(c[3])
        : "r"(a[0]), "r"(a[1]), "r"(a[2]), "r"(a[3]), "r"(b[0]), "r"(b[1]));
}
__device__ __forceinline__ void mma_f16(float* c, const uint32_t* a, const uint32_t* b) {
    asm volatile(
        "mma.sync.aligned.m16n8k16.row.col.f32.f16.f16.f32 "
        "{%0,%1,%2,%3}, {%4,%5,%6,%7}, {%8,%9}, {%0,%1,%2,%3};"
        : "+f"(c[0]), "+f"(c[1]), "+f"(c[2]), "+f"(c[3])
        : "r"(a[0]), "r"(a[1]), "r"(a[2]), "r"(a[3]), "r"(b[0]), "r"(b[1]));
}
#define LDS128(r, addr) \
    asm volatile("ld.shared.v4.b32 {%0,%1,%2,%3}, [%4];" \
        : "=r"((r)[0]), "=r"((r)[1]), "=r"((r)[2]), "=r"((r)[3]) : "r"(addr))
#define LDS64(r, addr) \
    asm volatile("ld.shared.v2.b32 {%0,%1}, [%2];" \
        : "=r"((r)[0]), "=r"((r)[1]) : "r"(addr))

// bf16 split: fp32 pair -> bf16-hi pair + bf16-lo (residual) pair
__device__ __forceinline__ void split2(float x, float y, uint32_t& h, uint32_t& l) {
    __nv_bfloat16 hx = __float2bfloat16_rn(x);
    __nv_bfloat16 hy = __float2bfloat16_rn(y);
    float lx = x - __bfloat162float(hx);
    float ly = y - __bfloat162float(hy);
    __nv_bfloat162 hp = __halves2bfloat162(hx, hy);
    __nv_bfloat162 lp = __floats2bfloat162_rn(lx, ly);
    h = *reinterpret_cast<uint32_t*>(&hp);
    l = *reinterpret_cast<uint32_t*>(&lp);
}
__device__ __forceinline__ uint32_t packh(float x, float y) {
    __half2 hp = __floats2half2_rn(x, y);
    return *reinterpret_cast<uint32_t*>(&hp);
}

// ---------------- pack A (smem-staged): [M,K] -> bf16 hi/lo A-frag tiles -----
__global__ __launch_bounds__(256) void pack_A_bf16(const float* __restrict__ src,
                                                   float* __restrict__ dst, int K)
{
    __shared__ float sa[128][33];
    const int kc = blockIdx.x, mt = blockIdx.y;
    const int tid = threadIdx.x;
    #pragma unroll
    for (int t = 0; t < 4; t++) {
        int u = tid + 256 * t;
        int r = u >> 3, c4 = u & 7;
        float4 v = *(const float4*)(src + (size_t)(mt * 128 + r) * K + kc * 32 + c4 * 4);
        sa[r][c4 * 4 + 0] = v.x; sa[r][c4 * 4 + 1] = v.y;
        sa[r][c4 * 4 + 2] = v.z; sa[r][c4 * 4 + 3] = v.w;
    }
    __syncthreads();
    uint4* tb = (uint4*)(dst + (size_t)(mt * (K / 32) + kc) * 4096);
    #pragma unroll
    for (int t = 0; t < 2; t++) {
        int u = tid + 256 * t;
        int ks2 = u >> 8, mtg = (u >> 5) & 7, lane = u & 31;
        int ml = mtg * 16 + (lane >> 2);
        int kl = ks2 * 16 + (lane & 3) * 2;
        uint32_t h0,h1,h2,h3,l0,l1,l2,l3;
        split2(sa[ml][kl],         sa[ml][kl + 1],       h0, l0);
        split2(sa[ml + 8][kl],     sa[ml + 8][kl + 1],   h1, l1);
        split2(sa[ml][kl + 8],     sa[ml][kl + 9],       h2, l2);
        split2(sa[ml + 8][kl + 8], sa[ml + 8][kl + 9],   h3, l3);
        int bi = ((ks2 * 8 + mtg) * 2) * 32 + lane;
        tb[bi]      = make_uint4(h0, h1, h2, h3);
        tb[bi + 32] = make_uint4(l0, l1, l2, l3);
    }
}

// ---------------- pack B bf16 hi/lo interleaved (16KB tiles) ------------------
__device__ __forceinline__ void pack_B_body(const float* __restrict__ w, int N,
                                            int kc, int ntl, uint4* __restrict__ tb)
{
    __shared__ float sb[32][129];
    const int tid = threadIdx.x;
    #pragma unroll
    for (int t = 0; t < 4; t++) {
        int u = tid + 256 * t;
        int r = u >> 5, c4 = u & 31;
        float4 v = *(const float4*)(w + (size_t)(kc * 32 + r) * N + ntl * 128 + c4 * 4);
        sb[r][c4 * 4 + 0] = v.x; sb[r][c4 * 4 + 1] = v.y;
        sb[r][c4 * 4 + 2] = v.z; sb[r][c4 * 4 + 3] = v.w;
    }
    __syncthreads();
    #pragma unroll
    for (int t = 0; t < 4; t++) {
        int u = tid + 256 * t;
        int ks2 = u >> 9, ntg = (u >> 5) & 15, lane = u & 31;
        int kl = ks2 * 16 + (lane & 3) * 2;
        int nl = ntg * 8 + (lane >> 2);
        uint32_t bh0, bl0, bh1, bl1;
        split2(sb[kl][nl],     sb[kl + 1][nl], bh0, bl0);
        split2(sb[kl + 8][nl], sb[kl + 9][nl], bh1, bl1);
        tb[(ks2 * 16 + ntg) * 32 + lane] = make_uint4(bh0, bh1, bl0, bl1);
    }
}

__global__ __launch_bounds__(256) void pack_B_qkv(const float* __restrict__ wq,
                                                  const float* __restrict__ wk,
                                                  const float* __restrict__ wv,
                                                  float* __restrict__ dst)
{
    const int kc = blockIdx.x, nt = blockIdx.y;
    uint4* tb = (uint4*)(dst + (size_t)(nt * KTILES + kc) * 4096);
    if (nt < 16)      pack_B_body(wq, DIM,    kc, nt,      tb);
    else if (nt < 24) pack_B_body(wk, NKV*HD, kc, nt - 16, tb);
    else              pack_B_body(wv, NKV*HD, kc, nt - 24, tb);
}

// ---------------- pack B fp16 single (8KB tiles) for WO -----------------------
__global__ __launch_bounds__(256) void pack_B_f16(const float* __restrict__ w,
                                                  float* __restrict__ dst, int N)
{
    __shared__ float sb[32][129];
    const int kc = blockIdx.x, nt = blockIdx.y;
    const int tid = threadIdx.x;
    #pragma unroll
    for (int t = 0; t < 4; t++) {
        int u = tid + 256 * t;
        int r = u >> 5, c4 = u & 31;
        float4 v = *(const float4*)(w + (size_t)(kc * 32 + r) * N + nt * 128 + c4 * 4);
        sb[r][c4 * 4 + 0] = v.x; sb[r][c4 * 4 + 1] = v.y;
        sb[r][c4 * 4 + 2] = v.z; sb[r][c4 * 4 + 3] = v.w;
    }
    __syncthreads();
    uint2* tb = (uint2*)(dst + (size_t)(nt * KTILES + kc) * 2048);
    #pragma unroll
    for (int t = 0; t < 4; t++) {
        int u = tid + 256 * t;
        int ks2 = u >> 9, ntg = (u >> 5) & 15, lane = u & 31;
        int kl = ks2 * 16 + (lane & 3) * 2;
        int nl = ntg * 8 + (lane >> 2);
        uint32_t bh0 = packh(sb[kl][nl],     sb[kl + 1][nl]);
        uint32_t bh1 = packh(sb[kl + 8][nl], sb[kl + 9][nl]);
        tb[(ks2 * 16 + ntg) * 32 + lane] = make_uint2(bh0, bh1);
    }
}

// ---------------- rope from smem tile ----------------------------------------
#define CPIT 132
__device__ __forceinline__ float rope_s(const float* __restrict__ scs, int row, int hd,
                                        const float* __restrict__ cosp,
                                        const float* __restrict__ sinp, int srow)
{
    int j = hd >> 1;
    float c = cosp[srow * 64 + j];
    float s = sinp[srow * 64 + j];
    float v0 = scs[row * CPIT + (hd & ~1)];
    float v1 = scs[row * CPIT + (hd | 1)];
    return (hd & 1) ? (v0 * s + v1 * c) : (v0 * c - v1 * s);
}

// ---------------- bf16x3 GEMM (QKV): fused rope + fp16-frag epilogue ---------
#define GSTAGES 3
#define STAGE_BYTES 32768

__global__ __launch_bounds__(256, 2) void gemm_qkv(
    const float* __restrict__ Ap, const float* __restrict__ Bp,
    int kTiles,
    float* __restrict__ Qr, float* __restrict__ Kr, float* __restrict__ Vr,
    const float* __restrict__ cosp, const float* __restrict__ sinp)
{
    extern __shared__ float dyn[];
    __shared__ __align__(8) uint64_t mbar[2 * GSTAGES];

    const int tid  = threadIdx.x;
    const int lane = tid & 31;
    const int warp = tid >> 5;
    const int wm = warp >> 2;
    const int wn = warp & 3;
    const int nt = blockIdx.x, mt = blockIdx.y;

    uint32_t sbase = (smem_u32(dyn) + 1023) & ~1023u;
    uint32_t mb = smem_u32(mbar);
    #define FULLB(s)  (mb + (s) * 8)
    #define EMPTYB(s) (mb + (GSTAGES + (s)) * 8)

    if (tid == 0) {
        #pragma unroll
        for (int s = 0; s < GSTAGES; s++) {
            MBAR_INIT(FULLB(s), 1);
            MBAR_INIT(EMPTYB(s), 256);
        }
    }
    __syncthreads();

    const char* At = (const char*)(Ap + (size_t)mt * kTiles * 4096);
    const char* Bt = (const char*)(Bp + (size_t)nt * kTiles * 4096);

    if (tid == 0) {
        fence_async();
        #pragma unroll
        for (int j = 0; j < GSTAGES; j++) {
            MBAR_EXPECT_TX(FULLB(j), STAGE_BYTES);
            bulk_g2s(sbase + j * STAGE_BYTES,         At + (size_t)j * 16384, 16384, FULLB(j));
            bulk_g2s(sbase + j * STAGE_BYTES + 16384, Bt + (size_t)j * 16384, 16384, FULLB(j));
        }
    }

    float acc[4][4][4];
    #pragma unroll
    for (int i = 0; i < 4; i++)
        #pragma unroll
        for (int j = 0; j < 4; j++)
            #pragma unroll
            for (int q = 0; q < 4; q++) acc[i][j][q] = 0.f;

    for (int i = 0; i < kTiles; i++) {
        const int s = i % GSTAGES;
        const uint32_t ph = (i / GSTAGES) & 1;
        mbar_wait(FULLB(s), ph);
        const uint32_t a_base = sbase + s * STAGE_BYTES;
        const uint32_t b_base = a_base + 16384;

        #pragma unroll
        for (int ks = 0; ks < 2; ks++) {
            uint32_t ah[4][4], al[4][4], bf[4][4];
            #pragma unroll
            for (int ii = 0; ii < 4; ii++) {
                LDS128(ah[ii], a_base + (uint32_t)((((ks * 8 + wm * 4 + ii) * 2 + 0) * 32 + lane) * 16));
                LDS128(al[ii], a_base + (uint32_t)((((ks * 8 + wm * 4 + ii) * 2 + 1) * 32 + lane) * 16));
            }
            #pragma unroll
            for (int jj = 0; jj < 4; jj++)
                LDS128(bf[jj], b_base + (uint32_t)(((ks * 16 + wn * 4 + jj) * 32 + lane) * 16));
            #pragma unroll
            for (int ii = 0; ii < 4; ii++)
                #pragma unroll
                for (int jj = 0; jj < 4; jj++) {
                    mma_bf16(acc[ii][jj], ah[ii], &bf[jj][0]);
                    mma_bf16(acc[ii][jj], ah[ii], &bf[jj][2]);
                    mma_bf16(acc[ii][jj], al[ii], &bf[jj][0]);
                }
        }
        MBAR_ARRIVE(EMPTYB(s));
        if (tid == 0) {
            int jn = i + GSTAGES;
            if (jn < kTiles) {
                mbar_wait(EMPTYB(s), ph);
                MBAR_EXPECT_TX(FULLB(s), STAGE_BYTES);
                bulk_g2s(a_base, At + (size_t)jn * 16384, 16384, FULLB(s));
                bulk_g2s(b_base, Bt + (size_t)jn * 16384, 16384, FULLB(s));
            }
        }
    }

    const int r = lane >> 2, cc = lane & 3;

    // fused QKV epilogue (Q/K/V -> fp16 frag tiles)
    __syncthreads();
    float* scs = dyn;
    #pragma unroll
    for (int ii = 0; ii < 4; ii++) {
        int rl = wm * 64 + ii * 16 + r;
        int cl = wn * 32 + 2 * cc;
        #pragma unroll
        for (int jj = 0; jj < 4; jj++) {
            *(float2*)&scs[rl * CPIT + cl + jj * 8]       = make_float2(acc[ii][jj][0], acc[ii][jj][1]);
            *(float2*)&scs[(rl + 8) * CPIT + cl + jj * 8] = make_float2(acc[ii][jj][2], acc[ii][jj][3]);
        }
    }
    __syncthreads();

    const int b = mt >> 4;
    const int row_base = mt * 128;

    if (nt < 16) {
        const float scale = 0.08838834764831845f;
        const int bh = b * 16 + nt;
        #pragma unroll
        for (int qhalf = 0; qhalf < 2; qhalf++) {
            uint4* out = (uint4*)(Qr + ((size_t)bh * 32 + (mt & 15) * 2 + qhalf) * 4096);
            #pragma unroll
            for (int t = 0; t < 4; t++) {
                int u = tid + 256 * t;
                int mtg = u >> 8, ds = (u >> 5) & 7, l2 = u & 31;
                int rl = qhalf * 64 + mtg * 16 + (l2 >> 2);
                int k  = ds * 16 + (l2 & 3) * 2;
                int s0 = (row_base + rl) & (SS - 1);
                int s1 = (row_base + rl + 8) & (SS - 1);
                uint32_t h0 = packh(rope_s(scs, rl,     k,     cosp, sinp, s0) * scale,
                                    rope_s(scs, rl,     k + 1, cosp, sinp, s0) * scale);
                uint32_t h1 = packh(rope_s(scs, rl + 8, k,     cosp, sinp, s1) * scale,
                                    rope_s(scs, rl + 8, k + 1, cosp, sinp, s1) * scale);
                uint32_t h2 = packh(rope_s(scs, rl,     k + 8, cosp, sinp, s0) * scale,
                                    rope_s(scs, rl,     k + 9, cosp, sinp, s0) * scale);
                uint32_t h3 = packh(rope_s(scs, rl + 8, k + 8, cosp, sinp, s1) * scale,
                                    rope_s(scs, rl + 8, k + 9, cosp, sinp, s1) * scale);
                out[(mtg * 8 + ds) * 32 + l2] = make_uint4(h0, h1, h2, h3);
            }
        }
    } else if (nt < 24) {
        const int bhk = b * 8 + (nt - 16);
        #pragma unroll
        for (int kvhalf = 0; kvhalf < 2; kvhalf++) {
            uint2* out = (uint2*)(Kr + ((size_t)bhk * 32 + (mt & 15) * 2 + kvhalf) * 4096);
            #pragma unroll
            for (int t = 0; t < 8; t++) {
                int u = tid + 256 * t;
                int ds = u >> 8, kvg = (u >> 5) & 7, l2 = u & 31;
                int rl = kvhalf * 64 + kvg * 8 + (l2 >> 2);
                int d  = ds * 16 + (l2 & 3) * 2;
                int srow = (row_base + rl) & (SS - 1);
                uint32_t kh0 = packh(rope_s(scs, rl, d,     cosp, sinp, srow),
                                     rope_s(scs, rl, d + 1, cosp, sinp, srow));
                uint32_t kh1 = packh(rope_s(scs, rl, d + 8, cosp, sinp, srow),
                                     rope_s(scs, rl, d + 9, cosp, sinp, srow));
                out[(ds * 8 + kvg) * 32 + l2] = make_uint2(kh0, kh1);
            }
        }
    } else {
        const int bhk = b * 8 + (nt - 24);
        #pragma unroll
        for (int vhalf = 0; vhalf < 2; vhalf++) {
            uint2* out = (uint2*)(Vr + ((size_t)bhk * 32 + (mt & 15) * 2 + vhalf) * 4096);
            #pragma unroll
            for (int it = 0; it < 8; it++) {
                int u = tid + 256 * it;
                int l2 = u & 31, ng = (u >> 5) & 15, ks = u >> 9;
                int kv0 = vhalf * 64 + ks * 16 + (l2 & 3) * 2;
                int d   = ng * 8 + (l2 >> 2);
                uint32_t vh0 = packh(scs[kv0 * CPIT + d],       scs[(kv0 + 1) * CPIT + d]);
                uint32_t vh1 = packh(scs[(kv0 + 8) * CPIT + d], scs[(kv0 + 9) * CPIT + d]);
                out[(ks * 16 + ng) * 32 + l2] = make_uint2(vh0, vh1);
            }
        }
    }
}

// ---------------- fp16x1 GEMM (WO): A single fp16, B single fp16 -------------
#define WSTAGES 5
#define WSTAGE_BYTES 16384      // A 8KB + B 8KB

__global__ __launch_bounds__(256, 2) void gemm_wo(
    const float* __restrict__ Ap, const float* __restrict__ Bp,
    float* __restrict__ C, int Ndim, int kTiles)
{
    extern __shared__ float dyn[];
    __shared__ __align__(8) uint64_t mbar[2 * WSTAGES];

    const int tid  = threadIdx.x;
    const int lane = tid & 31;
    const int warp = tid >> 5;
    const int wm = warp >> 2;
    const int wn = warp & 3;
    const int nt = blockIdx.x, mt = blockIdx.y;

    uint32_t sbase = (smem_u32(dyn) + 1023) & ~1023u;
    uint32_t mb = smem_u32(mbar);
    #define WFULL(s)  (mb + (s) * 8)
    #define WEMPTY(s) (mb + (WSTAGES + (s)) * 8)

    if (tid == 0) {
        #pragma unroll
        for (int s = 0; s < WSTAGES; s++) {
            MBAR_INIT(WFULL(s), 1);
            MBAR_INIT(WEMPTY(s), 256);
        }
    }
    __syncthreads();

    const char* At = (const char*)(Ap + (size_t)mt * kTiles * 2048);
    const char* Bt = (const char*)(Bp + (size_t)nt * kTiles * 2048);

    if (tid == 0) {
        fence_async();
        #pragma unroll
        for (int j = 0; j < WSTAGES; j++) {
            MBAR_EXPECT_TX(WFULL(j), WSTAGE_BYTES);
            bulk_g2s(sbase + j * WSTAGE_BYTES,        At + (size_t)j * 8192, 8192, WFULL(j));
            bulk_g2s(sbase + j * WSTAGE_BYTES + 8192, Bt + (size_t)j * 8192, 8192, WFULL(j));
        }
    }

    float acc[4][4][4];
    #pragma unroll
    for (int i = 0; i < 4; i++)
        #pragma unroll
        for (int j = 0; j < 4; j++)
            #pragma unroll
            for (int q = 0; q < 4; q++) acc[i][j][q] = 0.f;

    for (int i = 0; i < kTiles; i++) {
        const int s = i % WSTAGES;
        const uint32_t ph = (i / WSTAGES) & 1;
        mbar_wait(WFULL(s), ph);
        const uint32_t a_base = sbase + s * WSTAGE_BYTES;
        const uint32_t b_base = a_base + 8192;

        #pragma unroll
        for (int ks = 0; ks < 2; ks++) {
            uint32_t ah[4][4], bh[4][2];
            #pragma unroll
            for (int ii = 0; ii < 4; ii++)
                LDS128(ah[ii], a_base + (uint32_t)(((ks * 8 + wm * 4 + ii) * 32 + lane) * 16));
            #pragma unroll
            for (int jj = 0; jj < 4; jj++)
                LDS64(bh[jj], b_base + (uint32_t)(((ks * 16 + wn * 4 + jj) * 32 + lane) * 8));
            #pragma unroll
            for (int ii = 0; ii < 4; ii++)
                #pragma unroll
                for (int jj = 0; jj < 4; jj++)
                    mma_f16(acc[ii][jj], ah[ii], bh[jj]);
        }
        MBAR_ARRIVE(WEMPTY(s));
        if (tid == 0) {
            int jn = i + WSTAGES;
            if (jn < kTiles) {
                mbar_wait(WEMPTY(s), ph);
                MBAR_EXPECT_TX(WFULL(s), WSTAGE_BYTES);
                bulk_g2s(a_base, At + (size_t)jn * 8192, 8192, WFULL(s));
                bulk_g2s(b_base, Bt + (size_t)jn * 8192, 8192, WFULL(s));
            }
        }
    }

    const int r = lane >> 2, cc = lane & 3;
    #pragma unroll
    for (int ii = 0; ii < 4; ii++) {
        int m0 = mt * 128 + wm * 64 + ii * 16 + r;
        float* row0 = C + (size_t)m0 * Ndim + nt * 128 + wn * 32 + 2 * cc;
        float* row1 = row0 + 8 * (size_t)Ndim;
        #pragma unroll
        for (int jj = 0; jj < 4; jj++) {
            *(float2*)(row0 + jj * 8) = make_float2(acc[ii][jj][0], acc[ii][jj][1]);
            *(float2*)(row1 + jj * 8) = make_float2(acc[ii][jj][2], acc[ii][jj][3]);
        }
    }
}

// ---------------- tensor-core flash attention (fp16 QK + singleP-fp16V PV) ---
// BQ=128 (8 warps), BKV=64, 3-stage ring (K 16KB + V 16KB per stage) = 96KB.
#define ASTAGES 3
#define ATTN_SMEM (ASTAGES * 32768)

__global__ __launch_bounds__(256) void attn_mma(
    const float* __restrict__ Qr, const float* __restrict__ Kr,
    const float* __restrict__ Vr, float* __restrict__ Ap)
{
    extern __shared__ float sm[];
    __shared__ __align__(8) uint64_t bars[2 * ASTAGES];

    const int tid = threadIdx.x;
    const int lane = tid & 31, wq = tid >> 5;
    const int qt = 15 - blockIdx.x;                  // heavy CTAs first
    const int bh = blockIdx.y;
    const int b = bh >> 4, h = bh & 15;
    const int bhk = b * 8 + (h >> 1);
    const int niter = 2 * qt + 2;

    uint32_t sbase = smem_u32(sm);
    uint32_t mb = smem_u32(bars);
    #define AFULL(s)  (mb + (s) * 8)
    #define AEMPTY(s) (mb + (ASTAGES + (s)) * 8)

    uint32_t qf[8][4];
    {
        const uint4* qsrc = (const uint4*)(Qr + ((size_t)bh * 32 + qt * 2 + (wq >> 2)) * 4096);
        const int mtg = wq & 3;
        #pragma unroll
        for (int ds = 0; ds < 8; ds++) {
            uint4 v = __ldg(&qsrc[(mtg * 8 + ds) * 32 + lane]);
            qf[ds][0] = v.x; qf[ds][1] = v.y; qf[ds][2] = v.z; qf[ds][3] = v.w;
        }
    }

    if (tid == 0) {
        #pragma unroll
        for (int s = 0; s < ASTAGES; s++) {
            MBAR_INIT(AFULL(s), 1);
            MBAR_INIT(AEMPTY(s), 256);
        }
    }
    __syncthreads();
    if (tid == 0) {
        fence_async();
        int np = niter < ASTAGES ? niter : ASTAGES;
        for (int j = 0; j < np; j++) {
            MBAR_EXPECT_TX(AFULL(j), 32768);
            bulk_g2s(sbase + j * 32768,         Kr + ((size_t)bhk * 32 + j) * 4096, 16384, AFULL(j));
            bulk_g2s(sbase + j * 32768 + 16384, Vr + ((size_t)bhk * 32 + j) * 4096, 16384, AFULL(j));
        }
    }

    float o[16][4];
    #pragma unroll
    for (int i = 0; i < 16; i++)
        #pragma unroll
        for (int q = 0; q < 4; q++) o[i][q] = 0.f;
    float mr0 = -1e30f, mr1 = -1e30f, lr0 = 0.f, lr1 = 0.f;
    const int r0 = lane >> 2;
    const int c0 = (lane & 3) * 2;
    const int qrow = qt * 128 + wq * 16 + r0;

    for (int kb = 0; kb < niter; kb++) {
        const int s = kb % ASTAGES;
        const uint32_t ph = (kb / ASTAGES) & 1;
        mbar_wait(AFULL(s), ph);
        const uint32_t kbase = sbase + s * 32768;
        const uint32_t vbase = kbase + 16384;

        float sc[8][4];
        #pragma unroll
        for (int ng = 0; ng < 8; ng++)
            #pragma unroll
            for (int q = 0; q < 4; q++) sc[ng][q] = 0.f;
        #pragma unroll
        for (int ds = 0; ds < 8; ds++) {
            #pragma unroll
            for (int ng = 0; ng < 8; ng++) {
                uint32_t kf[2];
                LDS64(kf, kbase + (uint32_t)(((ds * 8 + ng) * 32 + lane) * 8));
                mma_f16(sc[ng], qf[ds], kf);
            }
        }
        if (kb >= 2 * qt) {
            #pragma unroll
            for (int ng = 0; ng < 8; ng++) {
                int col = kb * 64 + ng * 8 + c0;
                if (col     > qrow)     sc[ng][0] = -1e30f;
                if (col + 1 > qrow)     sc[ng][1] = -1e30f;
                if (col     > qrow + 8) sc[ng][2] = -1e30f;
                if (col + 1 > qrow + 8) sc[ng][3] = -1e30f;
            }
        }
        float mA = -1e30f, mB = -1e30f;
        #pragma unroll
        for (int ng = 0; ng < 8; ng++) {
            mA = fmaxf(mA, fmaxf(sc[ng][0], sc[ng][1]));
            mB = fmaxf(mB, fmaxf(sc[ng][2], sc[ng][3]));
        }
        mA = fmaxf(mA, __shfl_xor_sync(0xffffffffu, mA, 1));
        mA = fmaxf(mA, __shfl_xor_sync(0xffffffffu, mA, 2));
        mB = fmaxf(mB, __shfl_xor_sync(0xffffffffu, mB, 1));
        mB = fmaxf(mB, __shfl_xor_sync(0xffffffffu, mB, 2));
        float mnA = fmaxf(mr0, mA), mnB = fmaxf(mr1, mB);
        float fA = __expf(mr0 - mnA), fB = __expf(mr1 - mnB);
        mr0 = mnA; mr1 = mnB;
        float sA = 0.f, sB = 0.f;
        #pragma unroll
        for (int ng = 0; ng < 8; ng++) {
            sc[ng][0] = __expf(sc[ng][0] - mnA);
            sc[ng][1] = __expf(sc[ng][1] - mnA);
            sc[ng][2] = __expf(sc[ng][2] - mnB);
            sc[ng][3] = __expf(sc[ng][3] - mnB);
            sA += sc[ng][0] + sc[ng][1];
            sB += sc[ng][2] + sc[ng][3];
        }
        sA += __shfl_xor_sync(0xffffffffu, sA, 1);
        sA += __shfl_xor_sync(0xffffffffu, sA, 2);
        sB += __shfl_xor_sync(0xffffffffu, sB, 1);
        sB += __shfl_xor_sync(0xffffffffu, sB, 2);
        lr0 = lr0 * fA + sA;
        lr1 = lr1 * fB + sB;
        #pragma unroll
        for (int ng = 0; ng < 16; ng++) {
            o[ng][0] *= fA; o[ng][1] *= fA;
            o[ng][2] *= fB; o[ng][3] *= fB;
        }
        // pack P into single-fp16 A-frags (registers only)
        uint32_t aP[4][4];
        #pragma unroll
        for (int t = 0; t < 4; t++) {
            aP[t][0] = packh(sc[2*t][0],   sc[2*t][1]);
            aP[t][1] = packh(sc[2*t][2],   sc[2*t][3]);
            aP[t][2] = packh(sc[2*t+1][0], sc[2*t+1][1]);
            aP[t][3] = packh(sc[2*t+1][2], sc[2*t+1][3]);
        }
        // PV: single-fp16 P x fp16 V = 64 mmas
        #pragma unroll
        for (int t = 0; t < 4; t++) {
            #pragma unroll
            for (int ng = 0; ng < 16; ng++) {
                uint32_t vf[2];
                LDS64(vf, vbase + (uint32_t)(((t * 16 + ng) * 32 + lane) * 8));
                mma_f16(o[ng], aP[t], vf);
            }
        }
        MBAR_ARRIVE(AEMPTY(s));
        if (tid == 0 && kb + ASTAGES < niter) {
            int j = kb + ASTAGES;
            mbar_wait(AEMPTY(s), ph);
            MBAR_EXPECT_TX(AFULL(s), 32768);
            bulk_g2s(kbase, Kr + ((size_t)bhk * 32 + j) * 4096, 16384, AFULL(s));
            bulk_g2s(vbase, Vr + ((size_t)bhk * 32 + j) * 4096, 16384, AFULL(s));
        }
    }

    // epilogue: write WO-gemm A-fragments (single fp16, 8KB tiles)
    float iA = 1.0f / lr0, iB = 1.0f / lr1;
    const int mt = b * 16 + qt;
    #pragma unroll
    for (int t = 0; t < 8; t++) {
        float o0 = o[2*t][0] * iA,   o1 = o[2*t][1] * iA;
        float o2 = o[2*t][2] * iB,   o3 = o[2*t][3] * iB;
        float o4 = o[2*t+1][0] * iA, o5 = o[2*t+1][1] * iA;
        float o6 = o[2*t+1][2] * iB, o7 = o[2*t+1][3] * iB;
        uint32_t h0 = packh(o0, o1);
        uint32_t h1 = packh(o2, o3);
        uint32_t h2 = packh(o4, o5);
        uint32_t h3 = packh(o6, o7);
        int kglob = h * 128 + t * 16;
        int kc = kglob >> 5, ks2 = t & 1;
        uint4* tb = (uint4*)(Ap + ((size_t)mt * 64 + kc) * 2048);
        tb[(ks2 * 8 + wq) * 32 + lane] = make_uint4(h0, h1, h2, h3);
    }
}

// ---------------- launcher ---------------------------------------------------
extern "C" void kernel_launch(void* const* d_in, const int* in_sizes, int n_in,
                              void* d_out, int out_size)
{
    const float* x    = (const float*)d_in[0];
    const float* fcos = (const float*)d_in[1];
    const float* fsin = (const float*)d_in[2];
    const float* wq   = (const float*)d_in[3];
    const float* wk   = (const float*)d_in[4];
    const float* wv   = (const float*)d_in[5];
    const float* wo   = (const float*)d_in[6];
    float* out = (float*)d_out;

    float *pxp, *pattp, *pwqkvp, *pwop, *pQr, *pKr, *pVr;
    cudaGetSymbolAddress((void**)&pxp, g_xp);
    cudaGetSymbolAddress((void**)&pattp, g_attp);
    cudaGetSymbolAddress((void**)&pwqkvp, g_wqkvp);
    cudaGetSymbolAddress((void**)&pwop, g_wop);
    cudaGetSymbolAddress((void**)&pQr, g_Qr);
    cudaGetSymbolAddress((void**)&pKr, g_Kr);
    cudaGetSymbolAddress((void**)&pVr, g_Vr);

    const size_t gsmem = GSTAGES * STAGE_BYTES + 1024;
    const size_t wsmem = WSTAGES * WSTAGE_BYTES + 1024;
    cudaFuncSetAttribute(gemm_qkv, cudaFuncAttributeMaxDynamicSharedMemorySize, (int)gsmem);
    cudaFuncSetAttribute(gemm_wo,  cudaFuncAttributeMaxDynamicSharedMemorySize, (int)wsmem);
    cudaFuncSetAttribute(attn_mma, cudaFuncAttributeMaxDynamicSharedMemorySize, ATTN_SMEM);

    // packs
    pack_B_qkv<<<dim3(KTILES, 32), 256>>>(wq, wk, wv, pwqkvp);
    pack_B_f16<<<dim3(KTILES, DIM/128), 256>>>(wo, pwop, DIM);
    pack_A_bf16<<<dim3(KTILES, M_ROWS/128), 256>>>(x, pxp, DIM);

    // fused QKV projection (bf16x3) + rope + fp16 fragment repack (epilogue)
    gemm_qkv<<<dim3(CD/128, M_ROWS/128), 256, gsmem>>>(
        pxp, pwqkvp, KTILES, pQr, pKr, pVr, fcos, fsin);

    // tensor-core flash attention (fp16 QK, single-P PV; writes WO A-frags)
    attn_mma<<<dim3(16, BB * NH), 256, ATTN_SMEM>>>(pQr, pKr, pVr, pattp);

    // output projection (fp16 single x single)
    gemm_wo<<<dim3(DIM/128, M_ROWS/128), 256, wsmem>>>(pattp, pwop, out, DIM, KTILES);
}